// round 1
// baseline (speedup 1.0000x reference)
#include <cuda_runtime.h>
#include <cuda_bf16.h>
#include <math.h>

#define BATCH 8
#define NPTS  4096
#define KNN   20
#define FMAX  3.402823466e+38f

// ---------------- scratch (static device memory, no allocation) ----------------
__device__ float g_x1[BATCH*NPTS*64];
__device__ float g_d2[BATCH*NPTS];
__device__ int   g_idx1[BATCH*NPTS*KNN];
__device__ int   g_idx2[BATCH*NPTS*KNN];
__device__ float g_A2[BATCH*NPTS*128];
__device__ float g_C2[BATCH*NPTS*128];
__device__ float g_x2[BATCH*NPTS*128];
__device__ float g_pmax[BATCH*16*1024];
__device__ float g_gmax[BATCH*1024];

// =================== kernel 1: kNN on raw 2-D points ===================
__global__ void __launch_bounds__(256) knn1_kernel(const float* __restrict__ data) {
    __shared__ float2 sp[NPTS];
    int b = blockIdx.y;
    const float2* dp = (const float2*)(data + (size_t)b * NPTS * 2);
    for (int t = threadIdx.x; t < NPTS; t += 256) sp[t] = dp[t];
    __syncthreads();

    int i = blockIdx.x * 256 + threadIdx.x;
    float2 xi = sp[i];
    float d2i = xi.x * xi.x + xi.y * xi.y;

    float bd[KNN]; int bi[KNN];
#pragma unroll
    for (int n = 0; n < KNN; n++) { bd[n] = FMAX; bi[n] = 0x7fffffff; }
    float wv = FMAX; int wpos = 0;

    for (int j = 0; j < NPTS; j++) {
        float2 xj = sp[j];
        float d2j = xj.x * xj.x + xj.y * xj.y;
        float dot = xi.x * xj.x + xi.y * xj.y;
        float d = d2i + d2j - 2.0f * dot;
        if (d < wv) {
            bd[wpos] = d; bi[wpos] = j;
            float nw = bd[0]; int ni = bi[0]; int np = 0;
#pragma unroll
            for (int n = 1; n < KNN; n++) {
                float dn = bd[n]; int in_ = bi[n];
                if (dn > nw || (dn == nw && in_ > ni)) { nw = dn; ni = in_; np = n; }
            }
            wv = nw; wpos = np;
        }
    }
    int base = (b * NPTS + i) * KNN;
#pragma unroll
    for (int n = 0; n < KNN; n++) g_idx1[base + n] = bi[n];
}

// =================== kernel 2: EdgeConv1 fused MLP + max ===================
// block = 64 threads (thread = output channel), 8 points per block.
// W2/W3 columns live in registers; h1/h2 broadcast through smem as float4.
__global__ void __launch_bounds__(64) edge1_kernel(
    const float* __restrict__ data,
    const float* __restrict__ c1w1, const float* __restrict__ c1b1,
    const float* __restrict__ c1w2, const float* __restrict__ c1b2,
    const float* __restrict__ c1w3, const float* __restrict__ c1b3)
{
    int c = threadIdx.x;
    __shared__ __align__(16) float s_h1[64];
    __shared__ __align__(16) float s_h2[64];
    __shared__ float s_red[2];

    float w10 = c1w1[c], w11 = c1w1[64 + c], w12 = c1w1[128 + c], w13 = c1w1[192 + c];
    float wa = w10 - w12, wb = w11 - w13;
    float b1c = c1b1[c], b2c = c1b2[c], b3c = c1b3[c];

    float w2c[64], w3c[64];
#pragma unroll
    for (int d = 0; d < 64; d++) w2c[d] = c1w2[d * 64 + c];
#pragma unroll
    for (int d = 0; d < 64; d++) w3c[d] = c1w3[d * 64 + c];

    for (int p = 0; p < 8; p++) {
        int gp = blockIdx.x * 8 + p;
        int b = gp >> 12, i = gp & (NPTS - 1);
        float xi0 = data[(size_t)gp * 2 + 0];
        float xi1 = data[(size_t)gp * 2 + 1];
        float pc = fmaf(xi0, wa, fmaf(xi1, wb, b1c));
        float vmax = -FMAX;
        int ibase = gp * KNN;
        (void)i;
        for (int e = 0; e < KNN; e++) {
            int j = g_idx1[ibase + e];
            float xj0 = data[((size_t)b * NPTS + j) * 2 + 0];
            float xj1 = data[((size_t)b * NPTS + j) * 2 + 1];
            float h1 = fmaf(xj0, w12, fmaf(xj1, w13, pc));
            h1 = fmaxf(h1, 0.0f);
            s_h1[c] = h1;
            __syncthreads();
            float h2 = b2c;
            const float4* h4 = (const float4*)s_h1;
#pragma unroll
            for (int q = 0; q < 16; q++) {
                float4 v = h4[q];
                h2 = fmaf(v.x, w2c[4 * q + 0], h2);
                h2 = fmaf(v.y, w2c[4 * q + 1], h2);
                h2 = fmaf(v.z, w2c[4 * q + 2], h2);
                h2 = fmaf(v.w, w2c[4 * q + 3], h2);
            }
            h2 = fmaxf(h2, 0.0f);
            s_h2[c] = h2;
            __syncthreads();
            float h3 = b3c;
            const float4* g4 = (const float4*)s_h2;
#pragma unroll
            for (int q = 0; q < 16; q++) {
                float4 v = g4[q];
                h3 = fmaf(v.x, w3c[4 * q + 0], h3);
                h3 = fmaf(v.y, w3c[4 * q + 1], h3);
                h3 = fmaf(v.z, w3c[4 * q + 2], h3);
                h3 = fmaf(v.w, w3c[4 * q + 3], h3);
            }
            vmax = fmaxf(vmax, h3);
        }
        g_x1[(size_t)gp * 64 + c] = vmax;
        // row sum-of-squares for kNN2
        float v2 = vmax * vmax;
#pragma unroll
        for (int o = 16; o; o >>= 1) v2 += __shfl_xor_sync(0xffffffffu, v2, o);
        if ((c & 31) == 0) s_red[c >> 5] = v2;
        __syncthreads();
        if (c == 0) g_d2[gp] = s_red[0] + s_red[1];
        __syncthreads();
    }
}

// =================== kernel 3: EdgeConv2 per-point linear parts ===================
// A2 = x1 @ (Wtop - Wbot) + b ;  C2 = x1 @ Wbot
__global__ void __launch_bounds__(128) prep2_kernel(
    const float* __restrict__ c2w1, const float* __restrict__ c2b1)
{
    __shared__ float sx[8][64];
    int c = threadIdx.x;
    int base = blockIdx.x * 8;
    for (int idx = c; idx < 512; idx += 128) {
        int p = idx >> 6, d = idx & 63;
        sx[p][d] = g_x1[(size_t)(base + p) * 64 + d];
    }
    __syncthreads();
    float accA[8], accC[8];
    float bc = c2b1[c];
#pragma unroll
    for (int p = 0; p < 8; p++) { accA[p] = bc; accC[p] = 0.0f; }
    for (int d = 0; d < 64; d++) {
        float wt = c2w1[d * 128 + c];
        float wbv = c2w1[(d + 64) * 128 + c];
        float wd = wt - wbv;
#pragma unroll
        for (int p = 0; p < 8; p++) {
            float xv = sx[p][d];
            accA[p] = fmaf(xv, wd, accA[p]);
            accC[p] = fmaf(xv, wbv, accC[p]);
        }
    }
#pragma unroll
    for (int p = 0; p < 8; p++) {
        g_A2[(size_t)(base + p) * 128 + c] = accA[p];
        g_C2[(size_t)(base + p) * 128 + c] = accC[p];
    }
}

// =================== kernel 4: fused 64-D distance GEMM + top-20 ===================
// block: 256 threads, 64 i-rows, j tiles of 128; no materialized distance matrix.
#define KN2_AS   (64 * 68)
#define KN2_BS   (64 * 136)
#define KN2_LD   (64 * KNN)
#define KN2_SMEM_FLOATS (KN2_AS + KN2_BS + 2 * KN2_LD + 128 + 64)
#define KN2_SMEM_BYTES  (KN2_SMEM_FLOATS * 4)

__global__ void __launch_bounds__(256) knn2_kernel() {
    extern __shared__ float sm[];
    float* As  = sm;
    float* Bs  = sm + KN2_AS;                 // reused as Dist tile
    float* ld  = Bs + KN2_BS;
    int*   li  = (int*)(ld + KN2_LD);
    float* d2js= (float*)(li + KN2_LD);
    float* wvS = d2js + 128;

    int b = blockIdx.y;
    int it0 = blockIdx.x * 64;
    int tid = threadIdx.x;

    for (int idx = tid; idx < 64 * 64; idx += 256) {
        int i = idx >> 6, d = idx & 63;
        As[d * 68 + i] = g_x1[((size_t)b * NPTS + it0 + i) * 64 + d];
    }
    for (int idx = tid; idx < 64 * KNN; idx += 256) { ld[idx] = FMAX; li[idx] = 0x7fffffff; }
    if (tid < 64) wvS[tid] = FMAX;

    int tx = tid & 15, ty = tid >> 4;
    int i0 = ty * 4, j0 = tx * 8;
    float d2i[4];
#pragma unroll
    for (int ii = 0; ii < 4; ii++) d2i[ii] = g_d2[b * NPTS + it0 + i0 + ii];
    int lane = tid & 31, wid = tid >> 5;
    __syncthreads();

    for (int jt = 0; jt < 32; jt++) {
        int jb = jt * 128;
        for (int idx = tid; idx < 128 * 64; idx += 256) {
            int j = idx >> 6, d = idx & 63;
            Bs[d * 136 + j] = g_x1[((size_t)b * NPTS + jb + j) * 64 + d];
        }
        if (tid < 128) d2js[tid] = g_d2[b * NPTS + jb + tid];
        __syncthreads();

        float acc[4][8];
#pragma unroll
        for (int ii = 0; ii < 4; ii++)
#pragma unroll
            for (int jj = 0; jj < 8; jj++) acc[ii][jj] = 0.0f;

#pragma unroll 8
        for (int d = 0; d < 64; d++) {
            float4 a  = *(const float4*)(As + d * 68 + i0);
            float4 b0 = *(const float4*)(Bs + d * 136 + j0);
            float4 b1 = *(const float4*)(Bs + d * 136 + j0 + 4);
            float av[4] = {a.x, a.y, a.z, a.w};
            float bv[8] = {b0.x, b0.y, b0.z, b0.w, b1.x, b1.y, b1.z, b1.w};
#pragma unroll
            for (int ii = 0; ii < 4; ii++)
#pragma unroll
                for (int jj = 0; jj < 8; jj++)
                    acc[ii][jj] = fmaf(av[ii], bv[jj], acc[ii][jj]);
        }
        __syncthreads();
#pragma unroll
        for (int ii = 0; ii < 4; ii++)
#pragma unroll
            for (int jj = 0; jj < 8; jj++)
                Bs[(i0 + ii) * 136 + j0 + jj] = d2i[ii] + d2js[j0 + jj] - 2.0f * acc[ii][jj];
        __syncthreads();

        // selection: warp wid owns rows [wid*8, wid*8+8)
        for (int r = 0; r < 8; r++) {
            int row = wid * 8 + r;
            float worst = wvS[row];
            for (int ch = 0; ch < 4; ch++) {
                float dv = Bs[row * 136 + ch * 32 + lane];
                unsigned m = __ballot_sync(0xffffffffu, dv < worst);
                while (m) {
                    int s = __ffs(m) - 1;
                    float cand = __shfl_sync(0xffffffffu, dv, s);
                    int jg = jb + ch * 32 + s;
                    float nw = worst;
                    if (lane == 0) {
                        int lb = row * KNN;
                        int wp = 0; float wd = ld[lb]; int wi = li[lb];
#pragma unroll
                        for (int n = 1; n < KNN; n++) {
                            float dn = ld[lb + n]; int in_ = li[lb + n];
                            if (dn > wd || (dn == wd && in_ > wi)) { wd = dn; wi = in_; wp = n; }
                        }
                        ld[lb + wp] = cand; li[lb + wp] = jg;
                        wd = ld[lb]; wi = li[lb];
#pragma unroll
                        for (int n = 1; n < KNN; n++) {
                            float dn = ld[lb + n]; int in_ = li[lb + n];
                            if (dn > wd || (dn == wd && in_ > wi)) { wd = dn; wi = in_; }
                        }
                        nw = wd;
                    }
                    worst = __shfl_sync(0xffffffffu, nw, 0);
                    m &= ~(1u << s);
                    m &= __ballot_sync(0xffffffffu, dv < worst);
                }
            }
            if (lane == 0) wvS[row] = worst;
        }
        __syncthreads();
    }
    for (int idx = tid; idx < 64 * KNN; idx += 256) {
        int row = idx / KNN, n = idx % KNN;
        g_idx2[((size_t)b * NPTS + it0 + row) * KNN + n] = li[row * KNN + n];
    }
}

// =================== kernel 5: EdgeConv2 gather-max combine ===================
__global__ void __launch_bounds__(128) edge2max_kernel() {
    __shared__ int sj[KNN];
    int gp = blockIdx.x;
    int c = threadIdx.x;
    int b = gp >> 12;
    if (c < KNN) sj[c] = g_idx2[gp * KNN + c];
    __syncthreads();
    float m = -FMAX;
#pragma unroll
    for (int e = 0; e < KNN; e++)
        m = fmaxf(m, g_C2[((size_t)b * NPTS + sj[e]) * 128 + c]);
    g_x2[(size_t)gp * 128 + c] = g_A2[(size_t)gp * 128 + c] + m;
}

// =================== kernel 6: lin1 GEMM fused with max-over-points ===================
#define L1_WS (192 * 132)
#define L1_XS (192 * 68)
#define L1_SMEM_FLOATS (L1_WS + L1_XS + 16 * 128 + 128)
#define L1_SMEM_BYTES  (L1_SMEM_FLOATS * 4)

__global__ void __launch_bounds__(256) lin1max_kernel(const float* __restrict__ lin1_w) {
    extern __shared__ float sm[];
    float* Ws = sm;
    float* Xs = Ws + L1_WS;
    float* red = Xs + L1_XS;
    float* cmax = red + 16 * 128;

    int tid = threadIdx.x;
    int ic = blockIdx.x;   // i-chunk (0..15), 256 rows each
    int cc = blockIdx.y;   // col chunk (0..7), 128 cols each
    int b  = blockIdx.z;

    for (int idx = tid; idx < 192 * 128; idx += 256) {
        int k = idx >> 7, j = idx & 127;
        Ws[k * 132 + j] = lin1_w[k * 1024 + cc * 128 + j];
    }
    if (tid < 128) cmax[tid] = -FMAX;
    __syncthreads();

    int tx = tid & 15, ty = tid >> 4;
    int i0 = ty * 4, j0 = tx * 8;

    for (int st = 0; st < 4; st++) {
        int r0 = ic * 256 + st * 64;
        for (int idx = tid; idx < 64 * 192; idx += 256) {
            int i = idx / 192, k = idx % 192;
            float v = (k < 64) ? g_x1[((size_t)b * NPTS + r0 + i) * 64 + k]
                               : g_x2[((size_t)b * NPTS + r0 + i) * 128 + (k - 64)];
            Xs[k * 68 + i] = v;
        }
        __syncthreads();

        float acc[4][8];
#pragma unroll
        for (int ii = 0; ii < 4; ii++)
#pragma unroll
            for (int jj = 0; jj < 8; jj++) acc[ii][jj] = 0.0f;

#pragma unroll 8
        for (int k = 0; k < 192; k++) {
            float4 a  = *(const float4*)(Xs + k * 68 + i0);
            float4 w0 = *(const float4*)(Ws + k * 132 + j0);
            float4 w1 = *(const float4*)(Ws + k * 132 + j0 + 4);
            float av[4] = {a.x, a.y, a.z, a.w};
            float wv[8] = {w0.x, w0.y, w0.z, w0.w, w1.x, w1.y, w1.z, w1.w};
#pragma unroll
            for (int ii = 0; ii < 4; ii++)
#pragma unroll
                for (int jj = 0; jj < 8; jj++)
                    acc[ii][jj] = fmaf(av[ii], wv[jj], acc[ii][jj]);
        }
#pragma unroll
        for (int jj = 0; jj < 8; jj++) {
            float mv = fmaxf(fmaxf(acc[0][jj], acc[1][jj]), fmaxf(acc[2][jj], acc[3][jj]));
            red[ty * 128 + j0 + jj] = mv;
        }
        __syncthreads();
        if (tid < 128) {
            float mv = red[tid];
#pragma unroll
            for (int t = 1; t < 16; t++) mv = fmaxf(mv, red[t * 128 + tid]);
            cmax[tid] = fmaxf(cmax[tid], mv);
        }
        __syncthreads();
    }
    if (tid < 128)
        g_pmax[((size_t)b * 16 + ic) * 1024 + cc * 128 + tid] = cmax[tid];
}

// =================== kernel 7: reduce partial maxes + bias ===================
__global__ void __launch_bounds__(1024) redmax_kernel(const float* __restrict__ lin1_b) {
    int b = blockIdx.x, c = threadIdx.x;
    float m = -FMAX;
#pragma unroll
    for (int t = 0; t < 16; t++) m = fmaxf(m, g_pmax[((size_t)b * 16 + t) * 1024 + c]);
    g_gmax[b * 1024 + c] = m + lin1_b[c];
}

// =================== kernel 8: head MLP + log_softmax ===================
__global__ void __launch_bounds__(512) head_kernel(
    const float* __restrict__ mw1, const float* __restrict__ mb1,
    const float* __restrict__ mw2, const float* __restrict__ mb2,
    const float* __restrict__ mw3, const float* __restrict__ mb3,
    float* __restrict__ out)
{
    __shared__ float sg[1024];
    __shared__ float s1[512];
    __shared__ float s2[256];
    __shared__ float s3[10];
    int b = blockIdx.x, t = threadIdx.x;
    sg[t] = g_gmax[b * 1024 + t];
    sg[t + 512] = g_gmax[b * 1024 + t + 512];
    __syncthreads();

    float acc = mb1[t];
#pragma unroll 4
    for (int d = 0; d < 1024; d++) acc = fmaf(sg[d], mw1[d * 512 + t], acc);
    s1[t] = fmaxf(acc, 0.0f);
    __syncthreads();

    if (t < 256) {
        float a = mb2[t];
#pragma unroll 4
        for (int d = 0; d < 512; d++) a = fmaf(s1[d], mw2[d * 256 + t], a);
        s2[t] = fmaxf(a, 0.0f);
    }
    __syncthreads();

    if (t < 10) {
        float a = mb3[t];
        for (int d = 0; d < 256; d++) a = fmaf(s2[d], mw3[d * 10 + t], a);
        s3[t] = a;
    }
    __syncthreads();

    if (t == 0) {
        float mx = s3[0];
        for (int j = 1; j < 10; j++) mx = fmaxf(mx, s3[j]);
        float s = 0.0f;
        for (int j = 0; j < 10; j++) s += expf(s3[j] - mx);
        float l = logf(s) + mx;
        for (int j = 0; j < 10; j++) out[b * 10 + j] = s3[j] - l;
    }
}

// =================== launch ===================
extern "C" void kernel_launch(void* const* d_in, const int* in_sizes, int n_in,
                              void* d_out, int out_size) {
    const float* data   = (const float*)d_in[0];
    const float* c1w1   = (const float*)d_in[1];
    const float* c1b1   = (const float*)d_in[2];
    const float* c1w2   = (const float*)d_in[3];
    const float* c1b2   = (const float*)d_in[4];
    const float* c1w3   = (const float*)d_in[5];
    const float* c1b3   = (const float*)d_in[6];
    const float* c2w1   = (const float*)d_in[7];
    const float* c2b1   = (const float*)d_in[8];
    const float* lin1_w = (const float*)d_in[9];
    const float* lin1_b = (const float*)d_in[10];
    const float* mw1    = (const float*)d_in[11];
    const float* mb1    = (const float*)d_in[12];
    const float* mw2    = (const float*)d_in[13];
    const float* mb2    = (const float*)d_in[14];
    const float* mw3    = (const float*)d_in[15];
    const float* mb3    = (const float*)d_in[16];
    float* out = (float*)d_out;

    cudaFuncSetAttribute(knn2_kernel, cudaFuncAttributeMaxDynamicSharedMemorySize, KN2_SMEM_BYTES);
    cudaFuncSetAttribute(lin1max_kernel, cudaFuncAttributeMaxDynamicSharedMemorySize, L1_SMEM_BYTES);

    knn1_kernel<<<dim3(16, 8), 256>>>(data);
    edge1_kernel<<<BATCH * NPTS / 8, 64>>>(data, c1w1, c1b1, c1w2, c1b2, c1w3, c1b3);
    prep2_kernel<<<BATCH * NPTS / 8, 128>>>(c2w1, c2b1);
    knn2_kernel<<<dim3(64, 8), 256, KN2_SMEM_BYTES>>>();
    edge2max_kernel<<<BATCH * NPTS, 128>>>();
    lin1max_kernel<<<dim3(16, 8, 8), 256, L1_SMEM_BYTES>>>(lin1_w);
    redmax_kernel<<<8, 1024>>>(lin1_b);
    head_kernel<<<8, 512>>>(mw1, mb1, mw2, mb2, mw3, mb3, out);
}

// round 2
// speedup vs baseline: 2.5068x; 2.5068x over previous
#include <cuda_runtime.h>
#include <cuda_bf16.h>
#include <math.h>

#define BATCH 8
#define NPTS  4096
#define KNN   20
#define FMAX  3.402823466e+38f

// ---------------- scratch (static device memory, no allocation) ----------------
__device__ float g_x1[BATCH*NPTS*64];
__device__ float g_d2[BATCH*NPTS];
__device__ int   g_idx1[BATCH*NPTS*KNN];
__device__ int   g_idx2[BATCH*NPTS*KNN];
__device__ float g_A2[BATCH*NPTS*128];
__device__ float g_C2[BATCH*NPTS*128];
__device__ float g_x2[BATCH*NPTS*128];
__device__ float g_pmax[BATCH*16*1024];
__device__ float g_gmax[BATCH*1024];

// Warp-parallel top-K insert. List entry n lives in lane n (n < KNN).
// wl = lane currently holding the worst (lexicographic max (d, idx)) entry;
// wv = its distance. Insert replaces that lane, then one 5-step shfl-xor
// argmax reduction recomputes (wv, wl). All lanes converge to same result.
__device__ __forceinline__ void topk_insert(
    float cand, int cj, float& kdv, int& kiv, float& wv, int& wl, int lane)
{
    if (lane == wl) { kdv = cand; kiv = cj; }
    float md = (lane < KNN) ? kdv : -FMAX;
    int   mi = (lane < KNN) ? kiv : -1;
    int   ml = lane;
#pragma unroll
    for (int o = 16; o; o >>= 1) {
        float od = __shfl_xor_sync(0xffffffffu, md, o);
        int   oi = __shfl_xor_sync(0xffffffffu, mi, o);
        int   ol = __shfl_xor_sync(0xffffffffu, ml, o);
        bool t = (od > md) || (od == md && oi > mi);
        if (t) { md = od; mi = oi; ml = ol; }
    }
    wv = md; wl = ml;
}

// =================== kernel 1: kNN on raw 2-D points (warp rows) ===================
// block 256 = 8 warps; warp owns 8 rows; lane-distributed top-20 in registers.
__global__ void __launch_bounds__(256) knn1_kernel(const float* __restrict__ data) {
    __shared__ float2 sp[NPTS];
    int b = blockIdx.y;
    const float2* dp = (const float2*)(data + (size_t)b * NPTS * 2);
    for (int t = threadIdx.x; t < NPTS; t += 256) sp[t] = dp[t];
    __syncthreads();

    int tid = threadIdx.x, lane = tid & 31, wid = tid >> 5;
    int row0 = blockIdx.x * 64 + wid * 8;   // local point index base

    float2 xi[8]; float d2i[8];
#pragma unroll
    for (int r = 0; r < 8; r++) {
        xi[r] = sp[row0 + r];
        d2i[r] = xi[r].x * xi[r].x + xi[r].y * xi[r].y;
    }
    float kd[8], wv[8]; int ki[8], wl[8];
#pragma unroll
    for (int r = 0; r < 8; r++) { kd[r] = FMAX; ki[r] = 0x7fffffff; wv[r] = FMAX; wl[r] = 0; }

    for (int jc = 0; jc < NPTS / 32; jc++) {
        int jb = jc * 32;
        float2 xj = sp[jb + lane];
        float d2j = xj.x * xj.x + xj.y * xj.y;
#pragma unroll
        for (int r = 0; r < 8; r++) {
            float d = d2i[r] + d2j - 2.0f * (xi[r].x * xj.x + xi[r].y * xj.y);
            unsigned m = __ballot_sync(0xffffffffu, d < wv[r]);
            while (m) {
                int s = __ffs(m) - 1;
                float cand = __shfl_sync(0xffffffffu, d, s);
                topk_insert(cand, jb + s, kd[r], ki[r], wv[r], wl[r], lane);
                m &= ~(1u << s);
                m &= __ballot_sync(0xffffffffu, d < wv[r]);
            }
        }
    }
#pragma unroll
    for (int r = 0; r < 8; r++)
        if (lane < KNN)
            g_idx1[((size_t)b * NPTS + row0 + r) * KNN + lane] = ki[r];
}

// =================== kernel 2: EdgeConv1 as tiled GEMM ===================
// tile = 8 points x 20 edges = 160 rows. H1 built from 2-D inputs (cheap),
// then two 160x64x64 shared-memory GEMMs with 5x8 register accs; max over
// the 20 edge-rows of each point fused into the epilogue. Also emits row
// sum-of-squares (g_d2) for knn2.
#define E1_SW1 0
#define E1_SB1 256
#define E1_SB2 320
#define E1_SB3 384
#define E1_SPC 448
#define E1_SXJ 960
#define E1_SW2 1280
#define E1_SW3 5376
#define E1_SH1 9472
#define E1_SH2 20352
#define E1_FLOATS 31232
#define E1_BYTES (E1_FLOATS*4)

__global__ void __launch_bounds__(256) edge1_kernel(
    const float* __restrict__ data,
    const float* __restrict__ c1w1, const float* __restrict__ c1b1,
    const float* __restrict__ c1w2, const float* __restrict__ c1b2,
    const float* __restrict__ c1w3, const float* __restrict__ c1b3)
{
    extern __shared__ float sm[];
    int tid = threadIdx.x;
    int base = blockIdx.x * 8;          // global point index base
    int b = base >> 12;

    for (int idx = tid; idx < 256; idx += 256) sm[E1_SW1 + idx] = c1w1[idx];
    for (int idx = tid; idx < 4096; idx += 256) sm[E1_SW2 + idx] = c1w2[idx];
    for (int idx = tid; idx < 4096; idx += 256) sm[E1_SW3 + idx] = c1w3[idx];
    if (tid < 64) {
        sm[E1_SB1 + tid] = c1b1[tid];
        sm[E1_SB2 + tid] = c1b2[tid];
        sm[E1_SB3 + tid] = c1b3[tid];
    }
    __syncthreads();

    // per-point linear part pc[p][c] = xi0*(W1[0]-W1[2]) + xi1*(W1[1]-W1[3]) + b1
    for (int idx = tid; idx < 512; idx += 256) {
        int p = idx >> 6, c = idx & 63;
        float xi0 = data[(size_t)(base + p) * 2 + 0];
        float xi1 = data[(size_t)(base + p) * 2 + 1];
        float wa = sm[E1_SW1 + c] - sm[E1_SW1 + 128 + c];
        float wb = sm[E1_SW1 + 64 + c] - sm[E1_SW1 + 192 + c];
        sm[E1_SPC + p * 64 + c] = fmaf(xi0, wa, fmaf(xi1, wb, sm[E1_SB1 + c]));
    }
    // gather neighbor coords
    if (tid < 160) {
        int p = tid / 20, e = tid % 20;
        int j = g_idx1[(size_t)(base + p) * KNN + e];
        int gj = (b << 12) + j;
        sm[E1_SXJ + 2 * tid + 0] = data[(size_t)gj * 2 + 0];
        sm[E1_SXJ + 2 * tid + 1] = data[(size_t)gj * 2 + 1];
    }
    __syncthreads();

    // H1[row][c] = relu(xj0*W1[2][c] + xj1*W1[3][c] + pc[p][c])
    for (int idx = tid; idx < 160 * 64; idx += 256) {
        int row = idx >> 6, c = idx & 63;
        int p = row / 20;
        float xj0 = sm[E1_SXJ + 2 * row + 0];
        float xj1 = sm[E1_SXJ + 2 * row + 1];
        float h = fmaf(xj0, sm[E1_SW1 + 128 + c],
                  fmaf(xj1, sm[E1_SW1 + 192 + c], sm[E1_SPC + p * 64 + c]));
        sm[E1_SH1 + row * 68 + c] = fmaxf(h, 0.0f);
    }
    __syncthreads();

    int cg = tid & 7, rg = tid >> 3;     // 8 col-groups x 32 row-groups (5 rows each)
    // ---- GEMM 1: H2 = relu(H1 @ W2 + b2) ----
    {
        float acc[5][8];
#pragma unroll
        for (int s = 0; s < 5; s++)
#pragma unroll
            for (int jj = 0; jj < 8; jj++) acc[s][jj] = 0.0f;
#pragma unroll 8
        for (int k = 0; k < 64; k++) {
            float a[5];
#pragma unroll
            for (int s = 0; s < 5; s++) a[s] = sm[E1_SH1 + (rg * 5 + s) * 68 + k];
            float4 w0 = *(const float4*)&sm[E1_SW2 + k * 64 + cg * 8];
            float4 w1 = *(const float4*)&sm[E1_SW2 + k * 64 + cg * 8 + 4];
            float w[8] = {w0.x, w0.y, w0.z, w0.w, w1.x, w1.y, w1.z, w1.w};
#pragma unroll
            for (int s = 0; s < 5; s++)
#pragma unroll
                for (int jj = 0; jj < 8; jj++)
                    acc[s][jj] = fmaf(a[s], w[jj], acc[s][jj]);
        }
        float4 b20 = *(const float4*)&sm[E1_SB2 + cg * 8];
        float4 b21 = *(const float4*)&sm[E1_SB2 + cg * 8 + 4];
        float bb[8] = {b20.x, b20.y, b20.z, b20.w, b21.x, b21.y, b21.z, b21.w};
        __syncthreads();   // (no-op hazard: H2 region untouched yet; keeps phases clean)
#pragma unroll
        for (int s = 0; s < 5; s++) {
            float4 o0, o1;
            o0.x = fmaxf(acc[s][0] + bb[0], 0.0f);
            o0.y = fmaxf(acc[s][1] + bb[1], 0.0f);
            o0.z = fmaxf(acc[s][2] + bb[2], 0.0f);
            o0.w = fmaxf(acc[s][3] + bb[3], 0.0f);
            o1.x = fmaxf(acc[s][4] + bb[4], 0.0f);
            o1.y = fmaxf(acc[s][5] + bb[5], 0.0f);
            o1.z = fmaxf(acc[s][6] + bb[6], 0.0f);
            o1.w = fmaxf(acc[s][7] + bb[7], 0.0f);
            *(float4*)&sm[E1_SH2 + (rg * 5 + s) * 68 + cg * 8] = o0;
            *(float4*)&sm[E1_SH2 + (rg * 5 + s) * 68 + cg * 8 + 4] = o1;
        }
    }
    __syncthreads();
    // ---- GEMM 2: H3 = H2 @ W3 + b3, fused max over the thread's 5 rows ----
    {
        float acc[5][8];
#pragma unroll
        for (int s = 0; s < 5; s++)
#pragma unroll
            for (int jj = 0; jj < 8; jj++) acc[s][jj] = 0.0f;
#pragma unroll 8
        for (int k = 0; k < 64; k++) {
            float a[5];
#pragma unroll
            for (int s = 0; s < 5; s++) a[s] = sm[E1_SH2 + (rg * 5 + s) * 68 + k];
            float4 w0 = *(const float4*)&sm[E1_SW3 + k * 64 + cg * 8];
            float4 w1 = *(const float4*)&sm[E1_SW3 + k * 64 + cg * 8 + 4];
            float w[8] = {w0.x, w0.y, w0.z, w0.w, w1.x, w1.y, w1.z, w1.w};
#pragma unroll
            for (int s = 0; s < 5; s++)
#pragma unroll
                for (int jj = 0; jj < 8; jj++)
                    acc[s][jj] = fmaf(a[s], w[jj], acc[s][jj]);
        }
        float4 b30 = *(const float4*)&sm[E1_SB3 + cg * 8];
        float4 b31 = *(const float4*)&sm[E1_SB3 + cg * 8 + 4];
        float bb[8] = {b30.x, b30.y, b30.z, b30.w, b31.x, b31.y, b31.z, b31.w};
        float pm[8];
#pragma unroll
        for (int jj = 0; jj < 8; jj++) {
            float m = acc[0][jj];
#pragma unroll
            for (int s = 1; s < 5; s++) m = fmaxf(m, acc[s][jj]);
            pm[jj] = m + bb[jj];
        }
        // partial maxes into reused sH1 region: sP[rg][col] (32 x 64)
        *(float4*)&sm[E1_SH1 + rg * 64 + cg * 8]     = make_float4(pm[0], pm[1], pm[2], pm[3]);
        *(float4*)&sm[E1_SH1 + rg * 64 + cg * 8 + 4] = make_float4(pm[4], pm[5], pm[6], pm[7]);
    }
    __syncthreads();
    // final max over the 4 row-groups of each point, write x1 + stash for d2
    for (int idx = tid; idx < 512; idx += 256) {
        int p = idx >> 6, c = idx & 63;
        float m = sm[E1_SH1 + (p * 4 + 0) * 64 + c];
        m = fmaxf(m, sm[E1_SH1 + (p * 4 + 1) * 64 + c]);
        m = fmaxf(m, sm[E1_SH1 + (p * 4 + 2) * 64 + c]);
        m = fmaxf(m, sm[E1_SH1 + (p * 4 + 3) * 64 + c]);
        g_x1[(size_t)(base + p) * 64 + c] = m;
        sm[E1_SH2 + idx] = m;
    }
    __syncthreads();
    // row sum-of-squares (one warp per point)
    {
        int lane = tid & 31, w = tid >> 5;
        float v0 = sm[E1_SH2 + w * 64 + lane];
        float v1 = sm[E1_SH2 + w * 64 + 32 + lane];
        float s = v0 * v0 + v1 * v1;
#pragma unroll
        for (int o = 16; o; o >>= 1) s += __shfl_xor_sync(0xffffffffu, s, o);
        if (lane == 0) g_d2[base + w] = s;
    }
}

// =================== kernel 3: EdgeConv2 per-point linear parts ===================
__global__ void __launch_bounds__(128) prep2_kernel(
    const float* __restrict__ c2w1, const float* __restrict__ c2b1)
{
    __shared__ float sx[8][64];
    int c = threadIdx.x;
    int base = blockIdx.x * 8;
    for (int idx = c; idx < 512; idx += 128) {
        int p = idx >> 6, d = idx & 63;
        sx[p][d] = g_x1[(size_t)(base + p) * 64 + d];
    }
    __syncthreads();
    float accA[8], accC[8];
    float bc = c2b1[c];
#pragma unroll
    for (int p = 0; p < 8; p++) { accA[p] = bc; accC[p] = 0.0f; }
    for (int d = 0; d < 64; d++) {
        float wt = c2w1[d * 128 + c];
        float wbv = c2w1[(d + 64) * 128 + c];
        float wd = wt - wbv;
#pragma unroll
        for (int p = 0; p < 8; p++) {
            float xv = sx[p][d];
            accA[p] = fmaf(xv, wd, accA[p]);
            accC[p] = fmaf(xv, wbv, accC[p]);
        }
    }
#pragma unroll
    for (int p = 0; p < 8; p++) {
        g_A2[(size_t)(base + p) * 128 + c] = accA[p];
        g_C2[(size_t)(base + p) * 128 + c] = accC[p];
    }
}

// =================== kernel 4: fused 64-D distance GEMM + warp top-20 ===================
#define KN2_AS   (64 * 68)
#define KN2_BS   (64 * 136)
#define KN2_SMEM_FLOATS (KN2_AS + KN2_BS + 128)
#define KN2_SMEM_BYTES  (KN2_SMEM_FLOATS * 4)

__global__ void __launch_bounds__(256) knn2_kernel() {
    extern __shared__ float sm[];
    float* As   = sm;
    float* Bs   = sm + KN2_AS;          // reused as dist tile
    float* d2js = Bs + KN2_BS;

    int b = blockIdx.y;
    int it0 = blockIdx.x * 64;
    int tid = threadIdx.x;
    int lane = tid & 31, wid = tid >> 5;

    for (int idx = tid; idx < 64 * 64; idx += 256) {
        int i = idx >> 6, d = idx & 63;
        As[d * 68 + i] = g_x1[((size_t)b * NPTS + it0 + i) * 64 + d];
    }
    int tx = tid & 15, ty = tid >> 4;
    int i0 = ty * 4, j0 = tx * 8;
    float d2i[4];
#pragma unroll
    for (int ii = 0; ii < 4; ii++) d2i[ii] = g_d2[b * NPTS + it0 + i0 + ii];

    float kd[8], wv[8]; int ki[8], wl[8];
#pragma unroll
    for (int r = 0; r < 8; r++) { kd[r] = FMAX; ki[r] = 0x7fffffff; wv[r] = FMAX; wl[r] = 0; }
    __syncthreads();

    for (int jt = 0; jt < 32; jt++) {
        int jb = jt * 128;
        for (int idx = tid; idx < 128 * 64; idx += 256) {
            int j = idx >> 6, d = idx & 63;
            Bs[d * 136 + j] = g_x1[((size_t)b * NPTS + jb + j) * 64 + d];
        }
        if (tid < 128) d2js[tid] = g_d2[b * NPTS + jb + tid];
        __syncthreads();

        float acc[4][8];
#pragma unroll
        for (int ii = 0; ii < 4; ii++)
#pragma unroll
            for (int jj = 0; jj < 8; jj++) acc[ii][jj] = 0.0f;
#pragma unroll 8
        for (int d = 0; d < 64; d++) {
            float4 a  = *(const float4*)(As + d * 68 + i0);
            float4 b0 = *(const float4*)(Bs + d * 136 + j0);
            float4 b1 = *(const float4*)(Bs + d * 136 + j0 + 4);
            float av[4] = {a.x, a.y, a.z, a.w};
            float bv[8] = {b0.x, b0.y, b0.z, b0.w, b1.x, b1.y, b1.z, b1.w};
#pragma unroll
            for (int ii = 0; ii < 4; ii++)
#pragma unroll
                for (int jj = 0; jj < 8; jj++)
                    acc[ii][jj] = fmaf(av[ii], bv[jj], acc[ii][jj]);
        }
        __syncthreads();
#pragma unroll
        for (int ii = 0; ii < 4; ii++)
#pragma unroll
            for (int jj = 0; jj < 8; jj++)
                Bs[(i0 + ii) * 136 + j0 + jj] = d2i[ii] + d2js[j0 + jj] - 2.0f * acc[ii][jj];
        __syncthreads();

        // warp wid owns rows wid*8 .. wid*8+7; lane-distributed top-20
#pragma unroll
        for (int r = 0; r < 8; r++) {
            int row = wid * 8 + r;
#pragma unroll
            for (int ch = 0; ch < 4; ch++) {
                float dv = Bs[row * 136 + ch * 32 + lane];
                unsigned m = __ballot_sync(0xffffffffu, dv < wv[r]);
                while (m) {
                    int s = __ffs(m) - 1;
                    float cand = __shfl_sync(0xffffffffu, dv, s);
                    topk_insert(cand, jb + ch * 32 + s, kd[r], ki[r], wv[r], wl[r], lane);
                    m &= ~(1u << s);
                    m &= __ballot_sync(0xffffffffu, dv < wv[r]);
                }
            }
        }
        __syncthreads();
    }
#pragma unroll
    for (int r = 0; r < 8; r++)
        if (lane < KNN)
            g_idx2[((size_t)b * NPTS + it0 + wid * 8 + r) * KNN + lane] = ki[r];
}

// =================== kernel 5: EdgeConv2 gather-max combine ===================
__global__ void __launch_bounds__(128) edge2max_kernel() {
    __shared__ int sj[KNN];
    int gp = blockIdx.x;
    int c = threadIdx.x;
    int b = gp >> 12;
    if (c < KNN) sj[c] = g_idx2[(size_t)gp * KNN + c];
    __syncthreads();
    float m = -FMAX;
#pragma unroll
    for (int e = 0; e < KNN; e++)
        m = fmaxf(m, g_C2[((size_t)b * NPTS + sj[e]) * 128 + c]);
    g_x2[(size_t)gp * 128 + c] = g_A2[(size_t)gp * 128 + c] + m;
}

// =================== kernel 6: lin1 GEMM fused with max-over-points ===================
#define L1_WS (192 * 132)
#define L1_XS (192 * 68)
#define L1_SMEM_FLOATS (L1_WS + L1_XS + 16 * 128 + 128)
#define L1_SMEM_BYTES  (L1_SMEM_FLOATS * 4)

__global__ void __launch_bounds__(256) lin1max_kernel(const float* __restrict__ lin1_w) {
    extern __shared__ float sm[];
    float* Ws = sm;
    float* Xs = Ws + L1_WS;
    float* red = Xs + L1_XS;
    float* cmax = red + 16 * 128;

    int tid = threadIdx.x;
    int ic = blockIdx.x;   // i-chunk (0..15), 256 rows each
    int cc = blockIdx.y;   // col chunk (0..7), 128 cols each
    int b  = blockIdx.z;

    for (int idx = tid; idx < 192 * 128; idx += 256) {
        int k = idx >> 7, j = idx & 127;
        Ws[k * 132 + j] = lin1_w[k * 1024 + cc * 128 + j];
    }
    if (tid < 128) cmax[tid] = -FMAX;
    __syncthreads();

    int tx = tid & 15, ty = tid >> 4;
    int i0 = ty * 4, j0 = tx * 8;

    for (int st = 0; st < 4; st++) {
        int r0 = ic * 256 + st * 64;
        for (int idx = tid; idx < 64 * 192; idx += 256) {
            int i = idx / 192, k = idx % 192;
            float v = (k < 64) ? g_x1[((size_t)b * NPTS + r0 + i) * 64 + k]
                               : g_x2[((size_t)b * NPTS + r0 + i) * 128 + (k - 64)];
            Xs[k * 68 + i] = v;
        }
        __syncthreads();

        float acc[4][8];
#pragma unroll
        for (int ii = 0; ii < 4; ii++)
#pragma unroll
            for (int jj = 0; jj < 8; jj++) acc[ii][jj] = 0.0f;

#pragma unroll 8
        for (int k = 0; k < 192; k++) {
            float4 a  = *(const float4*)(Xs + k * 68 + i0);
            float4 w0 = *(const float4*)(Ws + k * 132 + j0);
            float4 w1 = *(const float4*)(Ws + k * 132 + j0 + 4);
            float av[4] = {a.x, a.y, a.z, a.w};
            float wv[8] = {w0.x, w0.y, w0.z, w0.w, w1.x, w1.y, w1.z, w1.w};
#pragma unroll
            for (int ii = 0; ii < 4; ii++)
#pragma unroll
                for (int jj = 0; jj < 8; jj++)
                    acc[ii][jj] = fmaf(av[ii], wv[jj], acc[ii][jj]);
        }
#pragma unroll
        for (int jj = 0; jj < 8; jj++) {
            float mv = fmaxf(fmaxf(acc[0][jj], acc[1][jj]), fmaxf(acc[2][jj], acc[3][jj]));
            red[ty * 128 + j0 + jj] = mv;
        }
        __syncthreads();
        if (tid < 128) {
            float mv = red[tid];
#pragma unroll
            for (int t = 1; t < 16; t++) mv = fmaxf(mv, red[t * 128 + tid]);
            cmax[tid] = fmaxf(cmax[tid], mv);
        }
        __syncthreads();
    }
    if (tid < 128)
        g_pmax[((size_t)b * 16 + ic) * 1024 + cc * 128 + tid] = cmax[tid];
}

// =================== kernel 7: reduce partial maxes + bias ===================
__global__ void __launch_bounds__(1024) redmax_kernel(const float* __restrict__ lin1_b) {
    int b = blockIdx.x, c = threadIdx.x;
    float m = -FMAX;
#pragma unroll
    for (int t = 0; t < 16; t++) m = fmaxf(m, g_pmax[((size_t)b * 16 + t) * 1024 + c]);
    g_gmax[b * 1024 + c] = m + lin1_b[c];
}

// =================== kernel 8: head MLP + log_softmax ===================
__global__ void __launch_bounds__(512) head_kernel(
    const float* __restrict__ mw1, const float* __restrict__ mb1,
    const float* __restrict__ mw2, const float* __restrict__ mb2,
    const float* __restrict__ mw3, const float* __restrict__ mb3,
    float* __restrict__ out)
{
    __shared__ float sg[1024];
    __shared__ float s1[512];
    __shared__ float s2[256];
    __shared__ float s3[10];
    int b = blockIdx.x, t = threadIdx.x;
    sg[t] = g_gmax[b * 1024 + t];
    sg[t + 512] = g_gmax[b * 1024 + t + 512];
    __syncthreads();

    float acc = mb1[t];
#pragma unroll 4
    for (int d = 0; d < 1024; d++) acc = fmaf(sg[d], mw1[d * 512 + t], acc);
    s1[t] = fmaxf(acc, 0.0f);
    __syncthreads();

    if (t < 256) {
        float a = mb2[t];
#pragma unroll 4
        for (int d = 0; d < 512; d++) a = fmaf(s1[d], mw2[d * 256 + t], a);
        s2[t] = fmaxf(a, 0.0f);
    }
    __syncthreads();

    if (t < 10) {
        float a = mb3[t];
        for (int d = 0; d < 256; d++) a = fmaf(s2[d], mw3[d * 10 + t], a);
        s3[t] = a;
    }
    __syncthreads();

    if (t == 0) {
        float mx = s3[0];
        for (int j = 1; j < 10; j++) mx = fmaxf(mx, s3[j]);
        float s = 0.0f;
        for (int j = 0; j < 10; j++) s += expf(s3[j] - mx);
        float l = logf(s) + mx;
        for (int j = 0; j < 10; j++) out[b * 10 + j] = s3[j] - l;
    }
}

// =================== launch ===================
extern "C" void kernel_launch(void* const* d_in, const int* in_sizes, int n_in,
                              void* d_out, int out_size) {
    const float* data   = (const float*)d_in[0];
    const float* c1w1   = (const float*)d_in[1];
    const float* c1b1   = (const float*)d_in[2];
    const float* c1w2   = (const float*)d_in[3];
    const float* c1b2   = (const float*)d_in[4];
    const float* c1w3   = (const float*)d_in[5];
    const float* c1b3   = (const float*)d_in[6];
    const float* c2w1   = (const float*)d_in[7];
    const float* c2b1   = (const float*)d_in[8];
    const float* lin1_w = (const float*)d_in[9];
    const float* lin1_b = (const float*)d_in[10];
    const float* mw1    = (const float*)d_in[11];
    const float* mb1    = (const float*)d_in[12];
    const float* mw2    = (const float*)d_in[13];
    const float* mb2    = (const float*)d_in[14];
    const float* mw3    = (const float*)d_in[15];
    const float* mb3    = (const float*)d_in[16];
    float* out = (float*)d_out;

    cudaFuncSetAttribute(edge1_kernel, cudaFuncAttributeMaxDynamicSharedMemorySize, E1_BYTES);
    cudaFuncSetAttribute(knn2_kernel, cudaFuncAttributeMaxDynamicSharedMemorySize, KN2_SMEM_BYTES);
    cudaFuncSetAttribute(lin1max_kernel, cudaFuncAttributeMaxDynamicSharedMemorySize, L1_SMEM_BYTES);

    knn1_kernel<<<dim3(64, 8), 256>>>(data);
    edge1_kernel<<<BATCH * NPTS / 8, 256, E1_BYTES>>>(data, c1w1, c1b1, c1w2, c1b2, c1w3, c1b3);
    prep2_kernel<<<BATCH * NPTS / 8, 128>>>(c2w1, c2b1);
    knn2_kernel<<<dim3(64, 8), 256, KN2_SMEM_BYTES>>>();
    edge2max_kernel<<<BATCH * NPTS, 128>>>();
    lin1max_kernel<<<dim3(16, 8, 8), 256, L1_SMEM_BYTES>>>(lin1_w);
    redmax_kernel<<<8, 1024>>>(lin1_b);
    head_kernel<<<8, 512>>>(mw1, mb1, mw2, mb2, mw3, mb3, out);
}

// round 3
// speedup vs baseline: 2.9573x; 1.1797x over previous
#include <cuda_runtime.h>
#include <cuda_bf16.h>
#include <math.h>

#define BATCH 8
#define NPTS  4096
#define KNN   20
#define FMAX  3.402823466e+38f

typedef unsigned long long u64t;

// packed f32x2 helpers (sm_100+): bit-exact fp32 FMA on both halves
__device__ __forceinline__ u64t pk2(float lo, float hi) {
    u64t r; asm("mov.b64 %0, {%1,%2};" : "=l"(r) : "f"(lo), "f"(hi)); return r;
}
__device__ __forceinline__ u64t fma2(u64t a, u64t b, u64t c) {
    u64t d; asm("fma.rn.f32x2 %0, %1, %2, %3;" : "=l"(d) : "l"(a), "l"(b), "l"(c)); return d;
}
__device__ __forceinline__ float2 up2(u64t v) {
    float2 f; asm("mov.b64 {%0,%1}, %2;" : "=f"(f.x), "=f"(f.y) : "l"(v)); return f;
}
union F4U { float4 f; u64t u[2]; };

// ---------------- scratch (static device memory, no allocation) ----------------
__device__ float g_x1[BATCH*NPTS*64];
__device__ float g_d2[BATCH*NPTS];
__device__ int   g_idx1[BATCH*NPTS*KNN];
__device__ int   g_idx2[BATCH*NPTS*KNN];
__device__ float g_A2[BATCH*NPTS*128];
__device__ float g_C2[BATCH*NPTS*128];
__device__ float g_x2[BATCH*NPTS*128];
__device__ float g_pmax[BATCH*16*1024];
__device__ float g_gmax[BATCH*1024];
__device__ float g_hpart[BATCH*8*512];

// Warp-parallel top-K insert. Entry n lives in lane n (n < KNN).
__device__ __forceinline__ void topk_insert(
    float cand, int cj, float& kdv, int& kiv, float& wv, int& wl, int lane)
{
    if (lane == wl) { kdv = cand; kiv = cj; }
    float md = (lane < KNN) ? kdv : -FMAX;
    int   mi = (lane < KNN) ? kiv : -1;
    int   ml = lane;
#pragma unroll
    for (int o = 16; o; o >>= 1) {
        float od = __shfl_xor_sync(0xffffffffu, md, o);
        int   oi = __shfl_xor_sync(0xffffffffu, mi, o);
        int   ol = __shfl_xor_sync(0xffffffffu, ml, o);
        bool t = (od > md) || (od == md && oi > mi);
        if (t) { md = od; mi = oi; ml = ol; }
    }
    wv = md; wl = ml;
}

// =================== kernel 1: kNN on raw 2-D points ===================
__global__ void __launch_bounds__(256) knn1_kernel(const float* __restrict__ data) {
    __shared__ float2 sp[NPTS];
    int b = blockIdx.y;
    const float2* dp = (const float2*)(data + (size_t)b * NPTS * 2);
    for (int t = threadIdx.x; t < NPTS; t += 256) sp[t] = dp[t];
    __syncthreads();

    int tid = threadIdx.x, lane = tid & 31, wid = tid >> 5;
    int row0 = blockIdx.x * 64 + wid * 8;

    float2 xi[8]; float d2i[8];
#pragma unroll
    for (int r = 0; r < 8; r++) {
        xi[r] = sp[row0 + r];
        d2i[r] = xi[r].x * xi[r].x + xi[r].y * xi[r].y;
    }
    float kd[8], wv[8]; int ki[8], wl[8];
#pragma unroll
    for (int r = 0; r < 8; r++) { kd[r] = FMAX; ki[r] = 0x7fffffff; wv[r] = FMAX; wl[r] = 0; }

    for (int jc = 0; jc < NPTS / 32; jc++) {
        int jb = jc * 32;
        float2 xj = sp[jb + lane];
        float d2j = xj.x * xj.x + xj.y * xj.y;
#pragma unroll
        for (int r = 0; r < 8; r++) {
            float d = d2i[r] + d2j - 2.0f * (xi[r].x * xj.x + xi[r].y * xj.y);
            unsigned m = __ballot_sync(0xffffffffu, d < wv[r]);
            while (m) {
                int s = __ffs(m) - 1;
                float cand = __shfl_sync(0xffffffffu, d, s);
                topk_insert(cand, jb + s, kd[r], ki[r], wv[r], wl[r], lane);
                m &= ~(1u << s);
                m &= __ballot_sync(0xffffffffu, d < wv[r]);
            }
        }
    }
#pragma unroll
    for (int r = 0; r < 8; r++)
        if (lane < KNN)
            g_idx1[((size_t)b * NPTS + row0 + r) * KNN + lane] = ki[r];
}

// =================== kernel 2: EdgeConv1 tiled GEMM (f32x2, single H buffer) ===================
#define E1_SW1 0
#define E1_SB1 256
#define E1_SB2 320
#define E1_SB3 384
#define E1_SPC 448
#define E1_SXJ 960
#define E1_SW2 1280
#define E1_SW3 5376
#define E1_SH  9472
#define E1_FLOATS (9472 + 160*68)
#define E1_BYTES (E1_FLOATS*4)

__global__ void __launch_bounds__(256) edge1_kernel(
    const float* __restrict__ data,
    const float* __restrict__ c1w1, const float* __restrict__ c1b1,
    const float* __restrict__ c1w2, const float* __restrict__ c1b2,
    const float* __restrict__ c1w3, const float* __restrict__ c1b3)
{
    extern __shared__ float sm[];
    int tid = threadIdx.x;
    int base = blockIdx.x * 8;
    int b = base >> 12;

    for (int idx = tid; idx < 256; idx += 256) sm[E1_SW1 + idx] = c1w1[idx];
    for (int idx = tid; idx < 4096; idx += 256) sm[E1_SW2 + idx] = c1w2[idx];
    for (int idx = tid; idx < 4096; idx += 256) sm[E1_SW3 + idx] = c1w3[idx];
    if (tid < 64) {
        sm[E1_SB1 + tid] = c1b1[tid];
        sm[E1_SB2 + tid] = c1b2[tid];
        sm[E1_SB3 + tid] = c1b3[tid];
    }
    __syncthreads();

    for (int idx = tid; idx < 512; idx += 256) {
        int p = idx >> 6, c = idx & 63;
        float xi0 = data[(size_t)(base + p) * 2 + 0];
        float xi1 = data[(size_t)(base + p) * 2 + 1];
        float wa = sm[E1_SW1 + c] - sm[E1_SW1 + 128 + c];
        float wb = sm[E1_SW1 + 64 + c] - sm[E1_SW1 + 192 + c];
        sm[E1_SPC + p * 64 + c] = fmaf(xi0, wa, fmaf(xi1, wb, sm[E1_SB1 + c]));
    }
    if (tid < 160) {
        int p = tid / 20, e = tid % 20;
        int j = g_idx1[(size_t)(base + p) * KNN + e];
        int gj = (b << 12) + j;
        sm[E1_SXJ + 2 * tid + 0] = data[(size_t)gj * 2 + 0];
        sm[E1_SXJ + 2 * tid + 1] = data[(size_t)gj * 2 + 1];
    }
    __syncthreads();

    // H1 into SH
    for (int idx = tid; idx < 160 * 64; idx += 256) {
        int row = idx >> 6, c = idx & 63;
        int p = row / 20;
        float xj0 = sm[E1_SXJ + 2 * row + 0];
        float xj1 = sm[E1_SXJ + 2 * row + 1];
        float h = fmaf(xj0, sm[E1_SW1 + 128 + c],
                  fmaf(xj1, sm[E1_SW1 + 192 + c], sm[E1_SPC + p * 64 + c]));
        sm[E1_SH + row * 68 + c] = fmaxf(h, 0.0f);
    }
    __syncthreads();

    int cg = tid & 7, rg = tid >> 3;
    // ---- GEMM 1: H2 = relu(H1 @ W2 + b2), f32x2 ----
    {
        u64t acc2[5][4];
#pragma unroll
        for (int s = 0; s < 5; s++)
#pragma unroll
            for (int q = 0; q < 4; q++) acc2[s][q] = 0ull;
#pragma unroll 8
        for (int k = 0; k < 64; k++) {
            float a[5];
#pragma unroll
            for (int s = 0; s < 5; s++) a[s] = sm[E1_SH + (rg * 5 + s) * 68 + k];
            F4U w0, w1;
            w0.f = *(const float4*)&sm[E1_SW2 + k * 64 + cg * 8];
            w1.f = *(const float4*)&sm[E1_SW2 + k * 64 + cg * 8 + 4];
            u64t wp[4] = {w0.u[0], w0.u[1], w1.u[0], w1.u[1]};
#pragma unroll
            for (int s = 0; s < 5; s++) {
                u64t as = pk2(a[s], a[s]);
#pragma unroll
                for (int q = 0; q < 4; q++) acc2[s][q] = fma2(as, wp[q], acc2[s][q]);
            }
        }
        float bb[8];
#pragma unroll
        for (int jj = 0; jj < 8; jj++) bb[jj] = sm[E1_SB2 + cg * 8 + jj];
        __syncthreads();   // all GEMM1 reads of SH done -> safe to overwrite with H2
#pragma unroll
        for (int s = 0; s < 5; s++) {
            float2 v0 = up2(acc2[s][0]), v1 = up2(acc2[s][1]);
            float2 v2 = up2(acc2[s][2]), v3 = up2(acc2[s][3]);
            float4 o0 = make_float4(fmaxf(v0.x + bb[0], 0.0f), fmaxf(v0.y + bb[1], 0.0f),
                                    fmaxf(v1.x + bb[2], 0.0f), fmaxf(v1.y + bb[3], 0.0f));
            float4 o1 = make_float4(fmaxf(v2.x + bb[4], 0.0f), fmaxf(v2.y + bb[5], 0.0f),
                                    fmaxf(v3.x + bb[6], 0.0f), fmaxf(v3.y + bb[7], 0.0f));
            *(float4*)&sm[E1_SH + (rg * 5 + s) * 68 + cg * 8] = o0;
            *(float4*)&sm[E1_SH + (rg * 5 + s) * 68 + cg * 8 + 4] = o1;
        }
    }
    __syncthreads();
    // ---- GEMM 2: H3 = H2 @ W3 + b3, fused 5-row max; partials into SW2 (dead) ----
    {
        u64t acc2[5][4];
#pragma unroll
        for (int s = 0; s < 5; s++)
#pragma unroll
            for (int q = 0; q < 4; q++) acc2[s][q] = 0ull;
#pragma unroll 8
        for (int k = 0; k < 64; k++) {
            float a[5];
#pragma unroll
            for (int s = 0; s < 5; s++) a[s] = sm[E1_SH + (rg * 5 + s) * 68 + k];
            F4U w0, w1;
            w0.f = *(const float4*)&sm[E1_SW3 + k * 64 + cg * 8];
            w1.f = *(const float4*)&sm[E1_SW3 + k * 64 + cg * 8 + 4];
            u64t wp[4] = {w0.u[0], w0.u[1], w1.u[0], w1.u[1]};
#pragma unroll
            for (int s = 0; s < 5; s++) {
                u64t as = pk2(a[s], a[s]);
#pragma unroll
                for (int q = 0; q < 4; q++) acc2[s][q] = fma2(as, wp[q], acc2[s][q]);
            }
        }
        float pm[8];
#pragma unroll
        for (int q = 0; q < 4; q++) {
            float2 m = up2(acc2[0][q]);
#pragma unroll
            for (int s = 1; s < 5; s++) {
                float2 v = up2(acc2[s][q]);
                m.x = fmaxf(m.x, v.x); m.y = fmaxf(m.y, v.y);
            }
            pm[2 * q] = m.x; pm[2 * q + 1] = m.y;
        }
#pragma unroll
        for (int jj = 0; jj < 8; jj++) pm[jj] += sm[E1_SB3 + cg * 8 + jj];
        *(float4*)&sm[E1_SW2 + rg * 64 + cg * 8]     = make_float4(pm[0], pm[1], pm[2], pm[3]);
        *(float4*)&sm[E1_SW2 + rg * 64 + cg * 8 + 4] = make_float4(pm[4], pm[5], pm[6], pm[7]);
    }
    __syncthreads();
    // final max over 4 row-groups per point; stash into SW3 (dead)
    for (int idx = tid; idx < 512; idx += 256) {
        int p = idx >> 6, c = idx & 63;
        float m = sm[E1_SW2 + (p * 4 + 0) * 64 + c];
        m = fmaxf(m, sm[E1_SW2 + (p * 4 + 1) * 64 + c]);
        m = fmaxf(m, sm[E1_SW2 + (p * 4 + 2) * 64 + c]);
        m = fmaxf(m, sm[E1_SW2 + (p * 4 + 3) * 64 + c]);
        g_x1[(size_t)(base + p) * 64 + c] = m;
        sm[E1_SW3 + idx] = m;
    }
    __syncthreads();
    {
        int lane = tid & 31, w = tid >> 5;
        float v0 = sm[E1_SW3 + w * 64 + lane];
        float v1 = sm[E1_SW3 + w * 64 + 32 + lane];
        float s = v0 * v0 + v1 * v1;
#pragma unroll
        for (int o = 16; o; o >>= 1) s += __shfl_xor_sync(0xffffffffu, s, o);
        if (lane == 0) g_d2[base + w] = s;
    }
}

// =================== kernel 3: EdgeConv2 per-point linear parts ===================
__global__ void __launch_bounds__(128) prep2_kernel(
    const float* __restrict__ c2w1, const float* __restrict__ c2b1)
{
    __shared__ float sx[8][64];
    int c = threadIdx.x;
    int base = blockIdx.x * 8;
    for (int idx = c; idx < 512; idx += 128) {
        int p = idx >> 6, d = idx & 63;
        sx[p][d] = g_x1[(size_t)(base + p) * 64 + d];
    }
    __syncthreads();
    float accA[8], accC[8];
    float bc = c2b1[c];
#pragma unroll
    for (int p = 0; p < 8; p++) { accA[p] = bc; accC[p] = 0.0f; }
    for (int d = 0; d < 64; d++) {
        float wt = c2w1[d * 128 + c];
        float wbv = c2w1[(d + 64) * 128 + c];
        float wd = wt - wbv;
#pragma unroll
        for (int p = 0; p < 8; p++) {
            float xv = sx[p][d];
            accA[p] = fmaf(xv, wd, accA[p]);
            accC[p] = fmaf(xv, wbv, accC[p]);
        }
    }
#pragma unroll
    for (int p = 0; p < 8; p++) {
        g_A2[(size_t)(base + p) * 128 + c] = accA[p];
        g_C2[(size_t)(base + p) * 128 + c] = accC[p];
    }
}

// =================== kernel 4: fused 64-D distance GEMM + warp top-20 (f32x2) ===================
#define KN2_PAD  140
#define KN2_AS   (64 * 68)
#define KN2_BS   (64 * KN2_PAD)
#define KN2_SMEM_FLOATS (KN2_AS + KN2_BS + 128)
#define KN2_SMEM_BYTES  (KN2_SMEM_FLOATS * 4)

__global__ void __launch_bounds__(256) knn2_kernel() {
    extern __shared__ float sm[];
    float* As   = sm;
    float* Bs   = sm + KN2_AS;          // reused as dist tile
    float* d2js = Bs + KN2_BS;

    int b = blockIdx.y;
    int it0 = blockIdx.x * 64;
    int tid = threadIdx.x;
    int lane = tid & 31, wid = tid >> 5;

    for (int idx = tid; idx < 64 * 64; idx += 256) {
        int i = idx >> 6, d = idx & 63;
        As[d * 68 + i] = g_x1[((size_t)b * NPTS + it0 + i) * 64 + d];
    }
    int tx = tid & 15, ty = tid >> 4;
    int i0 = ty * 4, j0 = tx * 8;
    float d2i[4];
#pragma unroll
    for (int ii = 0; ii < 4; ii++) d2i[ii] = g_d2[b * NPTS + it0 + i0 + ii];

    float kd[8], wv[8]; int ki[8], wl[8];
#pragma unroll
    for (int r = 0; r < 8; r++) { kd[r] = FMAX; ki[r] = 0x7fffffff; wv[r] = FMAX; wl[r] = 0; }
    __syncthreads();

    for (int jt = 0; jt < 32; jt++) {
        int jb = jt * 128;
        for (int idx = tid; idx < 128 * 64; idx += 256) {
            int j = idx >> 6, d = idx & 63;
            Bs[d * KN2_PAD + j] = g_x1[((size_t)b * NPTS + jb + j) * 64 + d];
        }
        if (tid < 128) d2js[tid] = g_d2[b * NPTS + jb + tid];
        __syncthreads();

        u64t acc2[4][4];
#pragma unroll
        for (int ii = 0; ii < 4; ii++)
#pragma unroll
            for (int q = 0; q < 4; q++) acc2[ii][q] = 0ull;
#pragma unroll 8
        for (int d = 0; d < 64; d++) {
            float4 a = *(const float4*)(As + d * 68 + i0);
            F4U b0, b1;
            b0.f = *(const float4*)(Bs + d * KN2_PAD + j0);
            b1.f = *(const float4*)(Bs + d * KN2_PAD + j0 + 4);
            u64t bp[4] = {b0.u[0], b0.u[1], b1.u[0], b1.u[1]};
            u64t a0 = pk2(a.x, a.x), a1 = pk2(a.y, a.y);
            u64t a2 = pk2(a.z, a.z), a3 = pk2(a.w, a.w);
#pragma unroll
            for (int q = 0; q < 4; q++) {
                acc2[0][q] = fma2(a0, bp[q], acc2[0][q]);
                acc2[1][q] = fma2(a1, bp[q], acc2[1][q]);
                acc2[2][q] = fma2(a2, bp[q], acc2[2][q]);
                acc2[3][q] = fma2(a3, bp[q], acc2[3][q]);
            }
        }
        __syncthreads();
#pragma unroll
        for (int ii = 0; ii < 4; ii++) {
            float2 v0 = up2(acc2[ii][0]), v1 = up2(acc2[ii][1]);
            float2 v2 = up2(acc2[ii][2]), v3 = up2(acc2[ii][3]);
            float di = d2i[ii];
            float4 o0 = make_float4(di + d2js[j0 + 0] - 2.0f * v0.x,
                                    di + d2js[j0 + 1] - 2.0f * v0.y,
                                    di + d2js[j0 + 2] - 2.0f * v1.x,
                                    di + d2js[j0 + 3] - 2.0f * v1.y);
            float4 o1 = make_float4(di + d2js[j0 + 4] - 2.0f * v2.x,
                                    di + d2js[j0 + 5] - 2.0f * v2.y,
                                    di + d2js[j0 + 6] - 2.0f * v3.x,
                                    di + d2js[j0 + 7] - 2.0f * v3.y);
            *(float4*)(Bs + (i0 + ii) * KN2_PAD + j0) = o0;
            *(float4*)(Bs + (i0 + ii) * KN2_PAD + j0 + 4) = o1;
        }
        __syncthreads();

#pragma unroll
        for (int r = 0; r < 8; r++) {
            int row = wid * 8 + r;
#pragma unroll
            for (int ch = 0; ch < 4; ch++) {
                float dv = Bs[row * KN2_PAD + ch * 32 + lane];
                unsigned m = __ballot_sync(0xffffffffu, dv < wv[r]);
                while (m) {
                    int s = __ffs(m) - 1;
                    float cand = __shfl_sync(0xffffffffu, dv, s);
                    topk_insert(cand, jb + ch * 32 + s, kd[r], ki[r], wv[r], wl[r], lane);
                    m &= ~(1u << s);
                    m &= __ballot_sync(0xffffffffu, dv < wv[r]);
                }
            }
        }
        __syncthreads();
    }
#pragma unroll
    for (int r = 0; r < 8; r++)
        if (lane < KNN)
            g_idx2[((size_t)b * NPTS + it0 + wid * 8 + r) * KNN + lane] = ki[r];
}

// =================== kernel 5: EdgeConv2 gather-max (4 points/block) ===================
__global__ void __launch_bounds__(128) edge2max_kernel() {
    __shared__ int sj[4][KNN];
    int p0 = blockIdx.x * 4;
    int c = threadIdx.x;
    if (c < 4 * KNN) sj[c / KNN][c % KNN] = g_idx2[(size_t)(p0 + c / KNN) * KNN + c % KNN];
    __syncthreads();
#pragma unroll
    for (int q = 0; q < 4; q++) {
        int gp = p0 + q;
        int b = gp >> 12;
        float m = -FMAX;
#pragma unroll
        for (int e = 0; e < KNN; e++)
            m = fmaxf(m, g_C2[((size_t)b * NPTS + sj[q][e]) * 128 + c]);
        g_x2[(size_t)gp * 128 + c] = g_A2[(size_t)gp * 128 + c] + m;
    }
}

// =================== kernel 6: lin1 GEMM fused with max-over-points (f32x2) ===================
#define L1_WS (192 * 132)
#define L1_XS (192 * 68)
#define L1_SMEM_FLOATS (L1_WS + L1_XS + 16 * 128 + 128)
#define L1_SMEM_BYTES  (L1_SMEM_FLOATS * 4)

__global__ void __launch_bounds__(256) lin1max_kernel(const float* __restrict__ lin1_w) {
    extern __shared__ float sm[];
    float* Ws = sm;
    float* Xs = Ws + L1_WS;
    float* red = Xs + L1_XS;
    float* cmax = red + 16 * 128;

    int tid = threadIdx.x;
    int ic = blockIdx.x;
    int cc = blockIdx.y;
    int b  = blockIdx.z;

    for (int idx = tid; idx < 192 * 128; idx += 256) {
        int k = idx >> 7, j = idx & 127;
        Ws[k * 132 + j] = lin1_w[k * 1024 + cc * 128 + j];
    }
    if (tid < 128) cmax[tid] = -FMAX;
    __syncthreads();

    int tx = tid & 15, ty = tid >> 4;
    int i0 = ty * 4, j0 = tx * 8;

    for (int st = 0; st < 4; st++) {
        int r0 = ic * 256 + st * 64;
        for (int idx = tid; idx < 64 * 192; idx += 256) {
            int i = idx / 192, k = idx % 192;
            float v = (k < 64) ? g_x1[((size_t)b * NPTS + r0 + i) * 64 + k]
                               : g_x2[((size_t)b * NPTS + r0 + i) * 128 + (k - 64)];
            Xs[k * 68 + i] = v;
        }
        __syncthreads();

        u64t acc2[4][4];
#pragma unroll
        for (int ii = 0; ii < 4; ii++)
#pragma unroll
            for (int q = 0; q < 4; q++) acc2[ii][q] = 0ull;

#pragma unroll 8
        for (int k = 0; k < 192; k++) {
            float4 a = *(const float4*)(Xs + k * 68 + i0);
            F4U w0, w1;
            w0.f = *(const float4*)(Ws + k * 132 + j0);
            w1.f = *(const float4*)(Ws + k * 132 + j0 + 4);
            u64t wp[4] = {w0.u[0], w0.u[1], w1.u[0], w1.u[1]};
            u64t a0 = pk2(a.x, a.x), a1 = pk2(a.y, a.y);
            u64t a2 = pk2(a.z, a.z), a3 = pk2(a.w, a.w);
#pragma unroll
            for (int q = 0; q < 4; q++) {
                acc2[0][q] = fma2(a0, wp[q], acc2[0][q]);
                acc2[1][q] = fma2(a1, wp[q], acc2[1][q]);
                acc2[2][q] = fma2(a2, wp[q], acc2[2][q]);
                acc2[3][q] = fma2(a3, wp[q], acc2[3][q]);
            }
        }
#pragma unroll
        for (int q = 0; q < 4; q++) {
            float2 m = up2(acc2[0][q]);
#pragma unroll
            for (int ii = 1; ii < 4; ii++) {
                float2 v = up2(acc2[ii][q]);
                m.x = fmaxf(m.x, v.x); m.y = fmaxf(m.y, v.y);
            }
            *(float2*)&red[ty * 128 + j0 + 2 * q] = m;
        }
        __syncthreads();
        if (tid < 128) {
            float mv = red[tid];
#pragma unroll
            for (int t = 1; t < 16; t++) mv = fmaxf(mv, red[t * 128 + tid]);
            cmax[tid] = fmaxf(cmax[tid], mv);
        }
        __syncthreads();
    }
    if (tid < 128)
        g_pmax[((size_t)b * 16 + ic) * 1024 + cc * 128 + tid] = cmax[tid];
}

// =================== kernel 7: reduce partial maxes + bias ===================
__global__ void __launch_bounds__(1024) redmax_kernel(const float* __restrict__ lin1_b) {
    int b = blockIdx.x, c = threadIdx.x;
    float m = -FMAX;
#pragma unroll
    for (int t = 0; t < 16; t++) m = fmaxf(m, g_pmax[((size_t)b * 16 + t) * 1024 + c]);
    g_gmax[b * 1024 + c] = m + lin1_b[c];
}

// =================== kernel 8a: head GEMV1 split over k-chunks ===================
__global__ void __launch_bounds__(512) head1_kernel(const float* __restrict__ mw1) {
    __shared__ float sg[128];
    int kc = blockIdx.x, b = blockIdx.y, t = threadIdx.x;
    if (t < 128) sg[t] = g_gmax[b * 1024 + kc * 128 + t];
    __syncthreads();
    float acc = 0.0f;
#pragma unroll 4
    for (int d = 0; d < 128; d++)
        acc = fmaf(sg[d], mw1[(size_t)(kc * 128 + d) * 512 + t], acc);
    g_hpart[(size_t)(b * 8 + kc) * 512 + t] = acc;
}

// =================== kernel 8b: head rest + log_softmax ===================
__global__ void __launch_bounds__(512) head2_kernel(
    const float* __restrict__ mb1,
    const float* __restrict__ mw2, const float* __restrict__ mb2,
    const float* __restrict__ mw3, const float* __restrict__ mb3,
    float* __restrict__ out)
{
    __shared__ float s1[512];
    __shared__ float s2[256];
    __shared__ float s3[10];
    int b = blockIdx.x, t = threadIdx.x;

    float a = mb1[t];
#pragma unroll
    for (int kc = 0; kc < 8; kc++) a += g_hpart[(size_t)(b * 8 + kc) * 512 + t];
    s1[t] = fmaxf(a, 0.0f);
    __syncthreads();

    if (t < 256) {
        float acc = mb2[t];
#pragma unroll 4
        for (int d = 0; d < 512; d++) acc = fmaf(s1[d], mw2[d * 256 + t], acc);
        s2[t] = fmaxf(acc, 0.0f);
    }
    __syncthreads();

    if (t < 10) {
        float acc = mb3[t];
        for (int d = 0; d < 256; d++) acc = fmaf(s2[d], mw3[d * 10 + t], acc);
        s3[t] = acc;
    }
    __syncthreads();

    if (t == 0) {
        float mx = s3[0];
        for (int j = 1; j < 10; j++) mx = fmaxf(mx, s3[j]);
        float s = 0.0f;
        for (int j = 0; j < 10; j++) s += expf(s3[j] - mx);
        float l = logf(s) + mx;
        for (int j = 0; j < 10; j++) out[b * 10 + j] = s3[j] - l;
    }
}

// =================== launch ===================
extern "C" void kernel_launch(void* const* d_in, const int* in_sizes, int n_in,
                              void* d_out, int out_size) {
    const float* data   = (const float*)d_in[0];
    const float* c1w1   = (const float*)d_in[1];
    const float* c1b1   = (const float*)d_in[2];
    const float* c1w2   = (const float*)d_in[3];
    const float* c1b2   = (const float*)d_in[4];
    const float* c1w3   = (const float*)d_in[5];
    const float* c1b3   = (const float*)d_in[6];
    const float* c2w1   = (const float*)d_in[7];
    const float* c2b1   = (const float*)d_in[8];
    const float* lin1_w = (const float*)d_in[9];
    const float* lin1_b = (const float*)d_in[10];
    const float* mw1    = (const float*)d_in[11];
    const float* mb1    = (const float*)d_in[12];
    const float* mw2    = (const float*)d_in[13];
    const float* mb2    = (const float*)d_in[14];
    const float* mw3    = (const float*)d_in[15];
    const float* mb3    = (const float*)d_in[16];
    float* out = (float*)d_out;

    cudaFuncSetAttribute(edge1_kernel, cudaFuncAttributeMaxDynamicSharedMemorySize, E1_BYTES);
    cudaFuncSetAttribute(knn2_kernel, cudaFuncAttributeMaxDynamicSharedMemorySize, KN2_SMEM_BYTES);
    cudaFuncSetAttribute(lin1max_kernel, cudaFuncAttributeMaxDynamicSharedMemorySize, L1_SMEM_BYTES);

    knn1_kernel<<<dim3(64, 8), 256>>>(data);
    edge1_kernel<<<BATCH * NPTS / 8, 256, E1_BYTES>>>(data, c1w1, c1b1, c1w2, c1b2, c1w3, c1b3);
    prep2_kernel<<<BATCH * NPTS / 8, 128>>>(c2w1, c2b1);
    knn2_kernel<<<dim3(64, 8), 256, KN2_SMEM_BYTES>>>();
    edge2max_kernel<<<BATCH * NPTS / 4, 128>>>();
    lin1max_kernel<<<dim3(16, 8, 8), 256, L1_SMEM_BYTES>>>(lin1_w);
    redmax_kernel<<<8, 1024>>>(lin1_b);
    head1_kernel<<<dim3(8, 8), 512>>>(mw1);
    head2_kernel<<<8, 512>>>(mb1, mw2, mb2, mw3, mb3, out);
}

// round 4
// speedup vs baseline: 3.6130x; 1.2217x over previous
#include <cuda_runtime.h>
#include <cuda_bf16.h>
#include <math.h>

#define BATCH 8
#define NPTS  4096
#define KNN   20
#define FMAX  3.402823466e+38f

typedef unsigned long long u64t;

// packed f32x2 helpers (sm_100+): bit-exact fp32 FMA on both halves
__device__ __forceinline__ u64t pk2(float lo, float hi) {
    u64t r; asm("mov.b64 %0, {%1,%2};" : "=l"(r) : "f"(lo), "f"(hi)); return r;
}
__device__ __forceinline__ u64t fma2(u64t a, u64t b, u64t c) {
    u64t d; asm("fma.rn.f32x2 %0, %1, %2, %3;" : "=l"(d) : "l"(a), "l"(b), "l"(c)); return d;
}
__device__ __forceinline__ float2 up2(u64t v) {
    float2 f; asm("mov.b64 {%0,%1}, %2;" : "=f"(f.x), "=f"(f.y) : "l"(v)); return f;
}
union F4U { float4 f; u64t u[2]; };

__device__ __forceinline__ void cp_async16(void* dst_smem, const void* src_gmem) {
    unsigned sa = (unsigned)__cvta_generic_to_shared(dst_smem);
    asm volatile("cp.async.cg.shared.global [%0], [%1], 16;" :: "r"(sa), "l"(src_gmem));
}
__device__ __forceinline__ void cp_async_commit() {
    asm volatile("cp.async.commit_group;" ::: "memory");
}
__device__ __forceinline__ void cp_async_wait0() {
    asm volatile("cp.async.wait_group 0;" ::: "memory");
}

// ---------------- scratch (static device memory, no allocation) ----------------
__device__ float g_x1[BATCH*NPTS*64];
__device__ float g_d2[BATCH*NPTS];
__device__ int   g_idx1[BATCH*NPTS*KNN];
__device__ int   g_idx2[BATCH*NPTS*KNN];
__device__ float g_A2[BATCH*NPTS*128];
__device__ float g_C2[BATCH*NPTS*128];
__device__ float g_x2[BATCH*NPTS*128];
__device__ float g_pmax[BATCH*16*1024];
__device__ float g_gmax[BATCH*1024];
__device__ float g_hpart[BATCH*8*512];

// Warp-parallel top-K insert. Entry n lives in lane n (n < KNN).
__device__ __forceinline__ void topk_insert(
    float cand, int cj, float& kdv, int& kiv, float& wv, int& wl, int lane)
{
    if (lane == wl) { kdv = cand; kiv = cj; }
    float md = (lane < KNN) ? kdv : -FMAX;
    int   mi = (lane < KNN) ? kiv : -1;
    int   ml = lane;
#pragma unroll
    for (int o = 16; o; o >>= 1) {
        float od = __shfl_xor_sync(0xffffffffu, md, o);
        int   oi = __shfl_xor_sync(0xffffffffu, mi, o);
        int   ol = __shfl_xor_sync(0xffffffffu, ml, o);
        bool t = (od > md) || (od == md && oi > mi);
        if (t) { md = od; mi = oi; ml = ol; }
    }
    wv = md; wl = ml;
}

// =================== kernel 1: kNN on raw 2-D points ===================
__global__ void __launch_bounds__(256) knn1_kernel(const float* __restrict__ data) {
    __shared__ float2 sp[NPTS];
    int b = blockIdx.y;
    const float2* dp = (const float2*)(data + (size_t)b * NPTS * 2);
    for (int t = threadIdx.x; t < NPTS; t += 256) sp[t] = dp[t];
    __syncthreads();

    int tid = threadIdx.x, lane = tid & 31, wid = tid >> 5;
    int row0 = blockIdx.x * 64 + wid * 8;

    float2 xi[8]; float d2i[8];
#pragma unroll
    for (int r = 0; r < 8; r++) {
        xi[r] = sp[row0 + r];
        d2i[r] = xi[r].x * xi[r].x + xi[r].y * xi[r].y;
    }
    float kd[8], wv[8]; int ki[8], wl[8];
#pragma unroll
    for (int r = 0; r < 8; r++) { kd[r] = FMAX; ki[r] = 0x7fffffff; wv[r] = FMAX; wl[r] = 0; }

    for (int jc = 0; jc < NPTS / 32; jc++) {
        int jb = jc * 32;
        float2 xj = sp[jb + lane];
        float d2j = xj.x * xj.x + xj.y * xj.y;
#pragma unroll
        for (int r = 0; r < 8; r++) {
            float d = d2i[r] + d2j - 2.0f * (xi[r].x * xj.x + xi[r].y * xj.y);
            unsigned m = __ballot_sync(0xffffffffu, d < wv[r]);
            while (m) {
                int s = __ffs(m) - 1;
                float cand = __shfl_sync(0xffffffffu, d, s);
                topk_insert(cand, jb + s, kd[r], ki[r], wv[r], wl[r], lane);
                m &= ~(1u << s);
                m &= __ballot_sync(0xffffffffu, d < wv[r]);
            }
        }
    }
#pragma unroll
    for (int r = 0; r < 8; r++)
        if (lane < KNN)
            g_idx1[((size_t)b * NPTS + row0 + r) * KNN + lane] = ki[r];
}

// =================== kernel 2: EdgeConv1 tiled GEMM (f32x2, single H buffer) ===================
#define E1_SW1 0
#define E1_SB1 256
#define E1_SB2 320
#define E1_SB3 384
#define E1_SPC 448
#define E1_SXJ 960
#define E1_SW2 1280
#define E1_SW3 5376
#define E1_SH  9472
#define E1_FLOATS (9472 + 160*68)
#define E1_BYTES (E1_FLOATS*4)

__global__ void __launch_bounds__(256) edge1_kernel(
    const float* __restrict__ data,
    const float* __restrict__ c1w1, const float* __restrict__ c1b1,
    const float* __restrict__ c1w2, const float* __restrict__ c1b2,
    const float* __restrict__ c1w3, const float* __restrict__ c1b3)
{
    extern __shared__ float sm[];
    int tid = threadIdx.x;
    int base = blockIdx.x * 8;
    int b = base >> 12;

    for (int idx = tid; idx < 256; idx += 256) sm[E1_SW1 + idx] = c1w1[idx];
    for (int idx = tid; idx < 4096; idx += 256) sm[E1_SW2 + idx] = c1w2[idx];
    for (int idx = tid; idx < 4096; idx += 256) sm[E1_SW3 + idx] = c1w3[idx];
    if (tid < 64) {
        sm[E1_SB1 + tid] = c1b1[tid];
        sm[E1_SB2 + tid] = c1b2[tid];
        sm[E1_SB3 + tid] = c1b3[tid];
    }
    __syncthreads();

    for (int idx = tid; idx < 512; idx += 256) {
        int p = idx >> 6, c = idx & 63;
        float xi0 = data[(size_t)(base + p) * 2 + 0];
        float xi1 = data[(size_t)(base + p) * 2 + 1];
        float wa = sm[E1_SW1 + c] - sm[E1_SW1 + 128 + c];
        float wb = sm[E1_SW1 + 64 + c] - sm[E1_SW1 + 192 + c];
        sm[E1_SPC + p * 64 + c] = fmaf(xi0, wa, fmaf(xi1, wb, sm[E1_SB1 + c]));
    }
    if (tid < 160) {
        int p = tid / 20, e = tid % 20;
        int j = g_idx1[(size_t)(base + p) * KNN + e];
        int gj = (b << 12) + j;
        sm[E1_SXJ + 2 * tid + 0] = data[(size_t)gj * 2 + 0];
        sm[E1_SXJ + 2 * tid + 1] = data[(size_t)gj * 2 + 1];
    }
    __syncthreads();

    for (int idx = tid; idx < 160 * 64; idx += 256) {
        int row = idx >> 6, c = idx & 63;
        int p = row / 20;
        float xj0 = sm[E1_SXJ + 2 * row + 0];
        float xj1 = sm[E1_SXJ + 2 * row + 1];
        float h = fmaf(xj0, sm[E1_SW1 + 128 + c],
                  fmaf(xj1, sm[E1_SW1 + 192 + c], sm[E1_SPC + p * 64 + c]));
        sm[E1_SH + row * 68 + c] = fmaxf(h, 0.0f);
    }
    __syncthreads();

    int cg = tid & 7, rg = tid >> 3;
    // ---- GEMM 1: H2 = relu(H1 @ W2 + b2), f32x2 ----
    {
        u64t acc2[5][4];
#pragma unroll
        for (int s = 0; s < 5; s++)
#pragma unroll
            for (int q = 0; q < 4; q++) acc2[s][q] = 0ull;
#pragma unroll 8
        for (int k = 0; k < 64; k++) {
            float a[5];
#pragma unroll
            for (int s = 0; s < 5; s++) a[s] = sm[E1_SH + (rg * 5 + s) * 68 + k];
            F4U w0, w1;
            w0.f = *(const float4*)&sm[E1_SW2 + k * 64 + cg * 8];
            w1.f = *(const float4*)&sm[E1_SW2 + k * 64 + cg * 8 + 4];
            u64t wp[4] = {w0.u[0], w0.u[1], w1.u[0], w1.u[1]};
#pragma unroll
            for (int s = 0; s < 5; s++) {
                u64t as = pk2(a[s], a[s]);
#pragma unroll
                for (int q = 0; q < 4; q++) acc2[s][q] = fma2(as, wp[q], acc2[s][q]);
            }
        }
        float bb[8];
#pragma unroll
        for (int jj = 0; jj < 8; jj++) bb[jj] = sm[E1_SB2 + cg * 8 + jj];
        __syncthreads();
#pragma unroll
        for (int s = 0; s < 5; s++) {
            float2 v0 = up2(acc2[s][0]), v1 = up2(acc2[s][1]);
            float2 v2 = up2(acc2[s][2]), v3 = up2(acc2[s][3]);
            float4 o0 = make_float4(fmaxf(v0.x + bb[0], 0.0f), fmaxf(v0.y + bb[1], 0.0f),
                                    fmaxf(v1.x + bb[2], 0.0f), fmaxf(v1.y + bb[3], 0.0f));
            float4 o1 = make_float4(fmaxf(v2.x + bb[4], 0.0f), fmaxf(v2.y + bb[5], 0.0f),
                                    fmaxf(v3.x + bb[6], 0.0f), fmaxf(v3.y + bb[7], 0.0f));
            *(float4*)&sm[E1_SH + (rg * 5 + s) * 68 + cg * 8] = o0;
            *(float4*)&sm[E1_SH + (rg * 5 + s) * 68 + cg * 8 + 4] = o1;
        }
    }
    __syncthreads();
    // ---- GEMM 2: H3 = H2 @ W3 + b3, fused 5-row max; partials into SW2 (dead) ----
    {
        u64t acc2[5][4];
#pragma unroll
        for (int s = 0; s < 5; s++)
#pragma unroll
            for (int q = 0; q < 4; q++) acc2[s][q] = 0ull;
#pragma unroll 8
        for (int k = 0; k < 64; k++) {
            float a[5];
#pragma unroll
            for (int s = 0; s < 5; s++) a[s] = sm[E1_SH + (rg * 5 + s) * 68 + k];
            F4U w0, w1;
            w0.f = *(const float4*)&sm[E1_SW3 + k * 64 + cg * 8];
            w1.f = *(const float4*)&sm[E1_SW3 + k * 64 + cg * 8 + 4];
            u64t wp[4] = {w0.u[0], w0.u[1], w1.u[0], w1.u[1]};
#pragma unroll
            for (int s = 0; s < 5; s++) {
                u64t as = pk2(a[s], a[s]);
#pragma unroll
                for (int q = 0; q < 4; q++) acc2[s][q] = fma2(as, wp[q], acc2[s][q]);
            }
        }
        float pm[8];
#pragma unroll
        for (int q = 0; q < 4; q++) {
            float2 m = up2(acc2[0][q]);
#pragma unroll
            for (int s = 1; s < 5; s++) {
                float2 v = up2(acc2[s][q]);
                m.x = fmaxf(m.x, v.x); m.y = fmaxf(m.y, v.y);
            }
            pm[2 * q] = m.x; pm[2 * q + 1] = m.y;
        }
#pragma unroll
        for (int jj = 0; jj < 8; jj++) pm[jj] += sm[E1_SB3 + cg * 8 + jj];
        *(float4*)&sm[E1_SW2 + rg * 64 + cg * 8]     = make_float4(pm[0], pm[1], pm[2], pm[3]);
        *(float4*)&sm[E1_SW2 + rg * 64 + cg * 8 + 4] = make_float4(pm[4], pm[5], pm[6], pm[7]);
    }
    __syncthreads();
    for (int idx = tid; idx < 512; idx += 256) {
        int p = idx >> 6, c = idx & 63;
        float m = sm[E1_SW2 + (p * 4 + 0) * 64 + c];
        m = fmaxf(m, sm[E1_SW2 + (p * 4 + 1) * 64 + c]);
        m = fmaxf(m, sm[E1_SW2 + (p * 4 + 2) * 64 + c]);
        m = fmaxf(m, sm[E1_SW2 + (p * 4 + 3) * 64 + c]);
        g_x1[(size_t)(base + p) * 64 + c] = m;
        sm[E1_SW3 + idx] = m;
    }
    __syncthreads();
    {
        int lane = tid & 31, w = tid >> 5;
        float v0 = sm[E1_SW3 + w * 64 + lane];
        float v1 = sm[E1_SW3 + w * 64 + 32 + lane];
        float s = v0 * v0 + v1 * v1;
#pragma unroll
        for (int o = 16; o; o >>= 1) s += __shfl_xor_sync(0xffffffffu, s, o);
        if (lane == 0) g_d2[base + w] = s;
    }
}

// =================== kernel 3: EdgeConv2 per-point linear parts ===================
__global__ void __launch_bounds__(128) prep2_kernel(
    const float* __restrict__ c2w1, const float* __restrict__ c2b1)
{
    __shared__ float sx[8][64];
    int c = threadIdx.x;
    int base = blockIdx.x * 8;
    for (int idx = c; idx < 512; idx += 128) {
        int p = idx >> 6, d = idx & 63;
        sx[p][d] = g_x1[(size_t)(base + p) * 64 + d];
    }
    __syncthreads();
    float accA[8], accC[8];
    float bc = c2b1[c];
#pragma unroll
    for (int p = 0; p < 8; p++) { accA[p] = bc; accC[p] = 0.0f; }
    for (int d = 0; d < 64; d++) {
        float wt = c2w1[d * 128 + c];
        float wbv = c2w1[(d + 64) * 128 + c];
        float wd = wt - wbv;
#pragma unroll
        for (int p = 0; p < 8; p++) {
            float xv = sx[p][d];
            accA[p] = fmaf(xv, wd, accA[p]);
            accC[p] = fmaf(xv, wbv, accC[p]);
        }
    }
#pragma unroll
    for (int p = 0; p < 8; p++) {
        g_A2[(size_t)(base + p) * 128 + c] = accA[p];
        g_C2[(size_t)(base + p) * 128 + c] = accC[p];
    }
}

// =================== kernel 4: knn2 — row-major dot-form GEMM + cp.async pipeline ===================
// block = 256 thr = 8 warps; warp owns 4 i-rows x 128 j (lane owns j = jj*32+lane).
// Tiles stored [row][k] with pad 68 (byte off = 16*(17*row+kq): conflict-free fills & reads).
// Distances stay in registers; selection via ballot directly on them.
#define KP 68
#define KN2_AS   (32 * KP)
#define KN2_BS   (128 * KP)
#define KN2_SMEM_FLOATS (KN2_AS + 2 * KN2_BS + 2 * 128)
#define KN2_SMEM_BYTES  (KN2_SMEM_FLOATS * 4)

__global__ void __launch_bounds__(256, 2) knn2_kernel() {
    extern __shared__ float sm[];
    float* As   = sm;
    float* Bs0  = sm + KN2_AS;
    float* d2s0 = sm + KN2_AS + 2 * KN2_BS;

    int b = blockIdx.y;
    int it0 = blockIdx.x * 32;
    int tid = threadIdx.x, lane = tid & 31, wid = tid >> 5;
    const float* xb = g_x1 + (size_t)b * NPTS * 64;

    // A tile fill (row-major, float4)
#pragma unroll
    for (int t = 0; t < 2; t++) {
        int idx = tid + t * 256;
        int i = idx >> 4, kq = idx & 15;
        *(float4*)(As + i * KP + kq * 4) =
            *(const float4*)(xb + (size_t)(it0 + i) * 64 + kq * 4);
    }
    float d2i[4];
#pragma unroll
    for (int r = 0; r < 4; r++) d2i[r] = g_d2[b * NPTS + it0 + wid * 4 + r];

    float kd[4], wv[4]; int ki[4], wl[4];
#pragma unroll
    for (int r = 0; r < 4; r++) { kd[r] = FMAX; ki[r] = 0x7fffffff; wv[r] = FMAX; wl[r] = 0; }

    // prologue: async-load tile 0 into buffer 0
    {
        float* B = Bs0;
#pragma unroll
        for (int t = 0; t < 8; t++) {
            int idx = tid + t * 256;
            int j = idx >> 4, kq = idx & 15;
            cp_async16(B + j * KP + kq * 4, xb + (size_t)j * 64 + kq * 4);
        }
        if (tid < 32) cp_async16(d2s0 + tid * 4, g_d2 + b * NPTS + tid * 4);
        cp_async_commit();
    }

    for (int jt = 0; jt < 32; jt++) {
        int buf = jt & 1;
        cp_async_wait0();
        __syncthreads();   // tile jt visible to all; all threads done with other buffer

        if (jt + 1 < 32) {
            int jb1 = (jt + 1) * 128;
            float* B = Bs0 + (buf ^ 1) * KN2_BS;
#pragma unroll
            for (int t = 0; t < 8; t++) {
                int idx = tid + t * 256;
                int j = idx >> 4, kq = idx & 15;
                cp_async16(B + j * KP + kq * 4, xb + (size_t)(jb1 + j) * 64 + kq * 4);
            }
            if (tid < 32) cp_async16(d2s0 + (buf ^ 1) * 128 + tid * 4,
                                     g_d2 + b * NPTS + jb1 + tid * 4);
            cp_async_commit();
        }

        const float* B = Bs0 + buf * KN2_BS;
        const float* d2s = d2s0 + buf * 128;
        int jb = jt * 128;

        u64t acc2[4][4];
#pragma unroll
        for (int r = 0; r < 4; r++)
#pragma unroll
            for (int jj = 0; jj < 4; jj++) acc2[r][jj] = 0ull;

#pragma unroll 8
        for (int kq = 0; kq < 16; kq++) {
            F4U a[4], bb[4];
#pragma unroll
            for (int r = 0; r < 4; r++)
                a[r].f = *(const float4*)(As + (wid * 4 + r) * KP + kq * 4);
#pragma unroll
            for (int jj = 0; jj < 4; jj++)
                bb[jj].f = *(const float4*)(B + (jj * 32 + lane) * KP + kq * 4);
#pragma unroll
            for (int r = 0; r < 4; r++)
#pragma unroll
                for (int jj = 0; jj < 4; jj++) {
                    acc2[r][jj] = fma2(a[r].u[0], bb[jj].u[0], acc2[r][jj]);
                    acc2[r][jj] = fma2(a[r].u[1], bb[jj].u[1], acc2[r][jj]);
                }
        }

        float d2jv[4];
#pragma unroll
        for (int jj = 0; jj < 4; jj++) d2jv[jj] = d2s[jj * 32 + lane];

#pragma unroll
        for (int r = 0; r < 4; r++) {
#pragma unroll
            for (int jj = 0; jj < 4; jj++) {
                float2 v = up2(acc2[r][jj]);
                float dv = d2i[r] + d2jv[jj] - 2.0f * (v.x + v.y);
                unsigned m = __ballot_sync(0xffffffffu, dv < wv[r]);
                while (m) {
                    int s = __ffs(m) - 1;
                    float cand = __shfl_sync(0xffffffffu, dv, s);
                    topk_insert(cand, jb + jj * 32 + s, kd[r], ki[r], wv[r], wl[r], lane);
                    m &= ~(1u << s);
                    m &= __ballot_sync(0xffffffffu, dv < wv[r]);
                }
            }
        }
    }
#pragma unroll
    for (int r = 0; r < 4; r++)
        if (lane < KNN)
            g_idx2[((size_t)b * NPTS + it0 + wid * 4 + r) * KNN + lane] = ki[r];
}

// =================== kernel 5: EdgeConv2 gather-max (4 points/block) ===================
__global__ void __launch_bounds__(128) edge2max_kernel() {
    __shared__ int sj[4][KNN];
    int p0 = blockIdx.x * 4;
    int c = threadIdx.x;
    if (c < 4 * KNN) sj[c / KNN][c % KNN] = g_idx2[(size_t)(p0 + c / KNN) * KNN + c % KNN];
    __syncthreads();
#pragma unroll
    for (int q = 0; q < 4; q++) {
        int gp = p0 + q;
        int b = gp >> 12;
        float m = -FMAX;
#pragma unroll
        for (int e = 0; e < KNN; e++)
            m = fmaxf(m, g_C2[((size_t)b * NPTS + sj[q][e]) * 128 + c]);
        g_x2[(size_t)gp * 128 + c] = g_A2[(size_t)gp * 128 + c] + m;
    }
}

// =================== kernel 6: lin1 GEMM fused with max-over-points (f32x2) ===================
#define L1_WS (192 * 132)
#define L1_XS (192 * 68)
#define L1_SMEM_FLOATS (L1_WS + L1_XS + 16 * 128 + 128)
#define L1_SMEM_BYTES  (L1_SMEM_FLOATS * 4)

__global__ void __launch_bounds__(256) lin1max_kernel(const float* __restrict__ lin1_w) {
    extern __shared__ float sm[];
    float* Ws = sm;
    float* Xs = Ws + L1_WS;
    float* red = Xs + L1_XS;
    float* cmax = red + 16 * 128;

    int tid = threadIdx.x;
    int ic = blockIdx.x;
    int cc = blockIdx.y;
    int b  = blockIdx.z;

    for (int idx = tid; idx < 192 * 128; idx += 256) {
        int k = idx >> 7, j = idx & 127;
        Ws[k * 132 + j] = lin1_w[k * 1024 + cc * 128 + j];
    }
    if (tid < 128) cmax[tid] = -FMAX;
    __syncthreads();

    int tx = tid & 15, ty = tid >> 4;
    int i0 = ty * 4, j0 = tx * 8;

    for (int st = 0; st < 4; st++) {
        int r0 = ic * 256 + st * 64;
        for (int idx = tid; idx < 64 * 192; idx += 256) {
            int i = idx / 192, k = idx % 192;
            float v = (k < 64) ? g_x1[((size_t)b * NPTS + r0 + i) * 64 + k]
                               : g_x2[((size_t)b * NPTS + r0 + i) * 128 + (k - 64)];
            Xs[k * 68 + i] = v;
        }
        __syncthreads();

        u64t acc2[4][4];
#pragma unroll
        for (int ii = 0; ii < 4; ii++)
#pragma unroll
            for (int q = 0; q < 4; q++) acc2[ii][q] = 0ull;

#pragma unroll 8
        for (int k = 0; k < 192; k++) {
            float4 a = *(const float4*)(Xs + k * 68 + i0);
            F4U w0, w1;
            w0.f = *(const float4*)(Ws + k * 132 + j0);
            w1.f = *(const float4*)(Ws + k * 132 + j0 + 4);
            u64t wp[4] = {w0.u[0], w0.u[1], w1.u[0], w1.u[1]};
            u64t a0 = pk2(a.x, a.x), a1 = pk2(a.y, a.y);
            u64t a2 = pk2(a.z, a.z), a3 = pk2(a.w, a.w);
#pragma unroll
            for (int q = 0; q < 4; q++) {
                acc2[0][q] = fma2(a0, wp[q], acc2[0][q]);
                acc2[1][q] = fma2(a1, wp[q], acc2[1][q]);
                acc2[2][q] = fma2(a2, wp[q], acc2[2][q]);
                acc2[3][q] = fma2(a3, wp[q], acc2[3][q]);
            }
        }
#pragma unroll
        for (int q = 0; q < 4; q++) {
            float2 m = up2(acc2[0][q]);
#pragma unroll
            for (int ii = 1; ii < 4; ii++) {
                float2 v = up2(acc2[ii][q]);
                m.x = fmaxf(m.x, v.x); m.y = fmaxf(m.y, v.y);
            }
            *(float2*)&red[ty * 128 + j0 + 2 * q] = m;
        }
        __syncthreads();
        if (tid < 128) {
            float mv = red[tid];
#pragma unroll
            for (int t = 1; t < 16; t++) mv = fmaxf(mv, red[t * 128 + tid]);
            cmax[tid] = fmaxf(cmax[tid], mv);
        }
        __syncthreads();
    }
    if (tid < 128)
        g_pmax[((size_t)b * 16 + ic) * 1024 + cc * 128 + tid] = cmax[tid];
}

// =================== kernel 7: reduce partial maxes + bias ===================
__global__ void __launch_bounds__(1024) redmax_kernel(const float* __restrict__ lin1_b) {
    int b = blockIdx.x, c = threadIdx.x;
    float m = -FMAX;
#pragma unroll
    for (int t = 0; t < 16; t++) m = fmaxf(m, g_pmax[((size_t)b * 16 + t) * 1024 + c]);
    g_gmax[b * 1024 + c] = m + lin1_b[c];
}

// =================== kernel 8a: head GEMV1 split over k-chunks ===================
__global__ void __launch_bounds__(512) head1_kernel(const float* __restrict__ mw1) {
    __shared__ float sg[128];
    int kc = blockIdx.x, b = blockIdx.y, t = threadIdx.x;
    if (t < 128) sg[t] = g_gmax[b * 1024 + kc * 128 + t];
    __syncthreads();
    float acc = 0.0f;
#pragma unroll 4
    for (int d = 0; d < 128; d++)
        acc = fmaf(sg[d], mw1[(size_t)(kc * 128 + d) * 512 + t], acc);
    g_hpart[(size_t)(b * 8 + kc) * 512 + t] = acc;
}

// =================== kernel 8b: head rest + log_softmax ===================
__global__ void __launch_bounds__(512) head2_kernel(
    const float* __restrict__ mb1,
    const float* __restrict__ mw2, const float* __restrict__ mb2,
    const float* __restrict__ mw3, const float* __restrict__ mb3,
    float* __restrict__ out)
{
    __shared__ float s1[512];
    __shared__ float s2[256];
    __shared__ float s3[10];
    int b = blockIdx.x, t = threadIdx.x;

    float a = mb1[t];
#pragma unroll
    for (int kc = 0; kc < 8; kc++) a += g_hpart[(size_t)(b * 8 + kc) * 512 + t];
    s1[t] = fmaxf(a, 0.0f);
    __syncthreads();

    if (t < 256) {
        float acc = mb2[t];
#pragma unroll 4
        for (int d = 0; d < 512; d++) acc = fmaf(s1[d], mw2[d * 256 + t], acc);
        s2[t] = fmaxf(acc, 0.0f);
    }
    __syncthreads();

    if (t < 10) {
        float acc = mb3[t];
        for (int d = 0; d < 256; d++) acc = fmaf(s2[d], mw3[d * 10 + t], acc);
        s3[t] = acc;
    }
    __syncthreads();

    if (t == 0) {
        float mx = s3[0];
        for (int j = 1; j < 10; j++) mx = fmaxf(mx, s3[j]);
        float s = 0.0f;
        for (int j = 0; j < 10; j++) s += expf(s3[j] - mx);
        float l = logf(s) + mx;
        for (int j = 0; j < 10; j++) out[b * 10 + j] = s3[j] - l;
    }
}

// =================== launch ===================
extern "C" void kernel_launch(void* const* d_in, const int* in_sizes, int n_in,
                              void* d_out, int out_size) {
    const float* data   = (const float*)d_in[0];
    const float* c1w1   = (const float*)d_in[1];
    const float* c1b1   = (const float*)d_in[2];
    const float* c1w2   = (const float*)d_in[3];
    const float* c1b2   = (const float*)d_in[4];
    const float* c1w3   = (const float*)d_in[5];
    const float* c1b3   = (const float*)d_in[6];
    const float* c2w1   = (const float*)d_in[7];
    const float* c2b1   = (const float*)d_in[8];
    const float* lin1_w = (const float*)d_in[9];
    const float* lin1_b = (const float*)d_in[10];
    const float* mw1    = (const float*)d_in[11];
    const float* mb1    = (const float*)d_in[12];
    const float* mw2    = (const float*)d_in[13];
    const float* mb2    = (const float*)d_in[14];
    const float* mw3    = (const float*)d_in[15];
    const float* mb3    = (const float*)d_in[16];
    float* out = (float*)d_out;

    cudaFuncSetAttribute(edge1_kernel, cudaFuncAttributeMaxDynamicSharedMemorySize, E1_BYTES);
    cudaFuncSetAttribute(knn2_kernel, cudaFuncAttributeMaxDynamicSharedMemorySize, KN2_SMEM_BYTES);
    cudaFuncSetAttribute(lin1max_kernel, cudaFuncAttributeMaxDynamicSharedMemorySize, L1_SMEM_BYTES);

    knn1_kernel<<<dim3(64, 8), 256>>>(data);
    edge1_kernel<<<BATCH * NPTS / 8, 256, E1_BYTES>>>(data, c1w1, c1b1, c1w2, c1b2, c1w3, c1b3);
    prep2_kernel<<<BATCH * NPTS / 8, 128>>>(c2w1, c2b1);
    knn2_kernel<<<dim3(128, 8), 256, KN2_SMEM_BYTES>>>();
    edge2max_kernel<<<BATCH * NPTS / 4, 128>>>();
    lin1max_kernel<<<dim3(16, 8, 8), 256, L1_SMEM_BYTES>>>(lin1_w);
    redmax_kernel<<<8, 1024>>>(lin1_b);
    head1_kernel<<<dim3(8, 8), 512>>>(mw1);
    head2_kernel<<<8, 512>>>(mb1, mw2, mb2, mw3, mb3, out);
}